// round 1
// baseline (speedup 1.0000x reference)
#include <cuda_runtime.h>
#include <cuda_bf16.h>
#include <cstddef>

#define SEQ 2048
#define EMB 768
#define NH  12
#define HD  64
#define MU_F (1.0f/2048.0f)

// ---------------- scratch (device globals; no allocation allowed) -------------
__device__ float g_Q[SEQ*EMB];
__device__ float g_K[SEQ*EMB];
__device__ float g_V[SEQ*EMB];
__device__ __nv_bfloat16 g_E[(size_t)NH*SEQ*SEQ];   // exp(QK^T/8), bf16, 100.7MB
__device__ float g_a[NH*SEQ];
__device__ float g_b[NH*SEQ];
__device__ float g_r[NH*SEQ];                       // reduction scratch
__device__ float g_ctx[SEQ*EMB];
__device__ float g_y[SEQ*EMB];

// ---------------- generic 128x128x8 sgemm, C = A@B + bias (+resid) -----------
__global__ __launch_bounds__(256) void sgemm128(
    const float* __restrict__ A, const float* __restrict__ B,
    const float* __restrict__ bias, const float* __restrict__ resid,
    float* __restrict__ C, int M, int N, int K)
{
    __shared__ float As[8][128];
    __shared__ float Bs[8][128];
    int tid = threadIdx.x;
    int tx = tid & 15, ty = tid >> 4;
    int row0 = blockIdx.y * 128, col0 = blockIdx.x * 128;

    const float* Ap = A + (size_t)(row0 + (tid >> 1)) * K + ((tid & 1) << 2);
    const float* Bp = B + (size_t)(tid >> 5) * N + col0 + ((tid & 31) << 2);

    float acc[8][8];
#pragma unroll
    for (int i = 0; i < 8; i++)
#pragma unroll
        for (int j = 0; j < 8; j++) acc[i][j] = 0.f;

    for (int k0 = 0; k0 < K; k0 += 8) {
        float4 av = *(const float4*)(Ap + k0);
        float4 bv = *(const float4*)(Bp + (size_t)k0 * N);
        int ar = tid >> 1, ac = (tid & 1) << 2;
        As[ac + 0][ar] = av.x; As[ac + 1][ar] = av.y;
        As[ac + 2][ar] = av.z; As[ac + 3][ar] = av.w;
        *(float4*)&Bs[tid >> 5][(tid & 31) << 2] = bv;
        __syncthreads();
#pragma unroll
        for (int kk = 0; kk < 8; kk++) {
            float4 a0 = *(const float4*)&As[kk][ty * 8];
            float4 a1 = *(const float4*)&As[kk][ty * 8 + 4];
            float4 b0 = *(const float4*)&Bs[kk][tx * 8];
            float4 b1 = *(const float4*)&Bs[kk][tx * 8 + 4];
            float ar_[8] = {a0.x,a0.y,a0.z,a0.w,a1.x,a1.y,a1.z,a1.w};
            float br_[8] = {b0.x,b0.y,b0.z,b0.w,b1.x,b1.y,b1.z,b1.w};
#pragma unroll
            for (int i = 0; i < 8; i++)
#pragma unroll
                for (int j = 0; j < 8; j++)
                    acc[i][j] += ar_[i] * br_[j];
        }
        __syncthreads();
    }

#pragma unroll
    for (int i = 0; i < 8; i++) {
        int r = row0 + ty * 8 + i;
#pragma unroll
        for (int j = 0; j < 8; j += 4) {
            int c = col0 + tx * 8 + j;
            float4 o;
            o.x = acc[i][j + 0] + bias[c + 0];
            o.y = acc[i][j + 1] + bias[c + 1];
            o.z = acc[i][j + 2] + bias[c + 2];
            o.w = acc[i][j + 3] + bias[c + 3];
            if (resid) {
                float4 rv = *(const float4*)&resid[(size_t)r * N + c];
                o.x += rv.x; o.y += rv.y; o.z += rv.z; o.w += rv.w;
            }
            *(float4*)&C[(size_t)r * N + c] = o;
        }
    }
}

// ------------- E = exp(Q K^T / 8) per head (bf16) + row sums into g_r --------
__global__ __launch_bounds__(256) void qk_exp_kernel(
    const float* __restrict__ Q, const float* __restrict__ Km)
{
    int h  = blockIdx.z;
    int bi = blockIdx.y, bj = blockIdx.x;
    __shared__ float Qs[8][128];
    __shared__ float Ks[8][128];
    __shared__ float rsum[128];
    int tid = threadIdx.x, tx = tid & 15, ty = tid >> 4;

    const float* Qp = Q + (size_t)(bi * 128 + (tid >> 1)) * EMB + h * HD + ((tid & 1) << 2);
    const float* Kp = Km + (size_t)(bj * 128 + (tid >> 1)) * EMB + h * HD + ((tid & 1) << 2);

    float acc[8][8];
#pragma unroll
    for (int i = 0; i < 8; i++)
#pragma unroll
        for (int j = 0; j < 8; j++) acc[i][j] = 0.f;

    for (int k0 = 0; k0 < HD; k0 += 8) {
        float4 qv = *(const float4*)(Qp + k0);
        float4 kv = *(const float4*)(Kp + k0);
        int r = tid >> 1, c = (tid & 1) << 2;
        Qs[c + 0][r] = qv.x; Qs[c + 1][r] = qv.y;
        Qs[c + 2][r] = qv.z; Qs[c + 3][r] = qv.w;
        Ks[c + 0][r] = kv.x; Ks[c + 1][r] = kv.y;
        Ks[c + 2][r] = kv.z; Ks[c + 3][r] = kv.w;
        __syncthreads();
#pragma unroll
        for (int kk = 0; kk < 8; kk++) {
            float4 a0 = *(const float4*)&Qs[kk][ty * 8];
            float4 a1 = *(const float4*)&Qs[kk][ty * 8 + 4];
            float4 b0 = *(const float4*)&Ks[kk][tx * 8];
            float4 b1 = *(const float4*)&Ks[kk][tx * 8 + 4];
            float ar_[8] = {a0.x,a0.y,a0.z,a0.w,a1.x,a1.y,a1.z,a1.w};
            float br_[8] = {b0.x,b0.y,b0.z,b0.w,b1.x,b1.y,b1.z,b1.w};
#pragma unroll
            for (int i = 0; i < 8; i++)
#pragma unroll
                for (int j = 0; j < 8; j++)
                    acc[i][j] += ar_[i] * br_[j];
        }
        __syncthreads();
    }

    if (tid < 128) rsum[tid] = 0.f;
    __syncthreads();

    float rpart[8];
#pragma unroll
    for (int i = 0; i < 8; i++) {
        float ev[8];
        rpart[i] = 0.f;
#pragma unroll
        for (int j = 0; j < 8; j++) {
            float e = __expf(acc[i][j] * 0.125f);
            ev[j] = e;
            rpart[i] += e;
        }
        __nv_bfloat162 pk[4];
#pragma unroll
        for (int q = 0; q < 4; q++)
            pk[q] = __floats2bfloat162_rn(ev[2 * q], ev[2 * q + 1]);
        size_t idx = ((size_t)h * SEQ + (size_t)(bi * 128 + ty * 8 + i)) * SEQ
                   + (size_t)(bj * 128 + tx * 8);
        *(uint4*)&g_E[idx] = *(uint4*)pk;
    }
#pragma unroll
    for (int i = 0; i < 8; i++) atomicAdd(&rsum[ty * 8 + i], rpart[i]);
    __syncthreads();
    if (tid < 128) atomicAdd(&g_r[h * SEQ + bi * 128 + tid], rsum[tid]);
}

// ---------------- row matvec: a = MU / (E b) --------------------------------
__global__ __launch_bounds__(256) void rowmv_kernel(
    const float* __restrict__ bvec, float* __restrict__ avec)
{
    int h = blockIdx.y;
    __shared__ float bs[SEQ];
    for (int j = threadIdx.x; j < SEQ; j += 256) bs[j] = bvec[h * SEQ + j];
    __syncthreads();
    int w = threadIdx.x >> 5, lane = threadIdx.x & 31;
#pragma unroll
    for (int rr = 0; rr < 2; rr++) {
        int row = blockIdx.x * 16 + w * 2 + rr;
        const uint4* Ep4 = (const uint4*)(g_E + ((size_t)h * SEQ + row) * SEQ);
        float sum = 0.f;
#pragma unroll 2
        for (int it = lane; it < SEQ / 8; it += 32) {
            uint4 u = Ep4[it];
            __nv_bfloat162 e2[4];
            *(uint4*)e2 = u;
            int base = it * 8;
#pragma unroll
            for (int q = 0; q < 4; q++) {
                float2 f = __bfloat1622float2(e2[q]);
                sum += f.x * bs[base + 2 * q] + f.y * bs[base + 2 * q + 1];
            }
        }
#pragma unroll
        for (int o = 16; o; o >>= 1) sum += __shfl_xor_sync(0xffffffffu, sum, o);
        if (lane == 0) avec[h * SEQ + row] = MU_F / sum;
    }
}

// ---------------- col matvec partial: r += E^T a (i-chunked) -----------------
__global__ __launch_bounds__(128) void colmv_kernel(
    const float* __restrict__ avec, float* __restrict__ cvec)
{
    int h = blockIdx.z;
    int j = blockIdx.x * 128 + threadIdx.x;
    int i0 = blockIdx.y * (SEQ / 8);   // 256-row chunk
    __shared__ float as_[SEQ / 8];
    for (int i = threadIdx.x; i < SEQ / 8; i += 128) as_[i] = avec[h * SEQ + i0 + i];
    __syncthreads();
    const __nv_bfloat16* Ep = g_E + (size_t)h * SEQ * SEQ + (size_t)i0 * SEQ + j;
    float sum = 0.f;
#pragma unroll 8
    for (int i = 0; i < SEQ / 8; i++)
        sum += __bfloat162float(Ep[(size_t)i * SEQ]) * as_[i];
    atomicAdd(&cvec[h * SEQ + j], sum);
}

// ---------------- finish: dst = MU / r ; r = 0 -------------------------------
__global__ void fin_kernel(float* __restrict__ dst, float* __restrict__ r)
{
    int i = blockIdx.x * 256 + threadIdx.x;
    float c = r[i];
    r[i] = 0.f;
    dst[i] = MU_F / c;
}

__global__ void zero_kernel(float* __restrict__ r)
{
    r[blockIdx.x * 256 + threadIdx.x] = 0.f;
}

// -------- ctx = n * diag(a) * E * diag(b) * V, per head ----------------------
__global__ __launch_bounds__(256) void av_kernel(
    const float* __restrict__ V, const float* __restrict__ avec,
    const float* __restrict__ bvec, float* __restrict__ ctx)
{
    int h  = blockIdx.y;
    int i0 = blockIdx.x * 64;
    __shared__ float Ps[64][65];   // [k=j][i]
    __shared__ float Vs[64][68];   // [k=j][d], b folded in
    __shared__ float as_[64];

    int tid = threadIdx.x, tx = tid & 15, ty = tid >> 4;
    if (tid < 64) as_[tid] = avec[h * SEQ + i0 + tid] * 2048.0f;

    int li = tid >> 2;            // 0..63
    int lg = (tid & 3) << 4;      // 0,16,32,48
    const __nv_bfloat16* Ebase = g_E + ((size_t)h * SEQ + i0 + li) * SEQ + lg;
    const float* Vbase = V + (size_t)li * EMB + h * HD + lg;

    float acc[4][4];
#pragma unroll
    for (int r = 0; r < 4; r++)
#pragma unroll
        for (int c = 0; c < 4; c++) acc[r][c] = 0.f;

    for (int j0 = 0; j0 < SEQ; j0 += 64) {
        uint4 eu0 = *(const uint4*)(Ebase + j0);
        uint4 eu1 = *(const uint4*)(Ebase + j0 + 8);
        float bk = bvec[h * SEQ + j0 + li];
        const float* Vp = Vbase + (size_t)j0 * EMB;
        float4 v0 = *(const float4*)(Vp + 0);
        float4 v1 = *(const float4*)(Vp + 4);
        float4 v2 = *(const float4*)(Vp + 8);
        float4 v3 = *(const float4*)(Vp + 12);

        __syncthreads();   // previous compute done before overwrite

        __nv_bfloat162 e2[8];
        *(uint4*)&e2[0] = eu0;
        *(uint4*)&e2[4] = eu1;
#pragma unroll
        for (int q = 0; q < 8; q++) {
            float2 f = __bfloat1622float2(e2[q]);
            Ps[lg + 2 * q + 0][li] = f.x;
            Ps[lg + 2 * q + 1][li] = f.y;
        }
        float4 w0 = make_float4(v0.x*bk, v0.y*bk, v0.z*bk, v0.w*bk);
        float4 w1 = make_float4(v1.x*bk, v1.y*bk, v1.z*bk, v1.w*bk);
        float4 w2 = make_float4(v2.x*bk, v2.y*bk, v2.z*bk, v2.w*bk);
        float4 w3 = make_float4(v3.x*bk, v3.y*bk, v3.z*bk, v3.w*bk);
        *(float4*)&Vs[li][lg + 0]  = w0;
        *(float4*)&Vs[li][lg + 4]  = w1;
        *(float4*)&Vs[li][lg + 8]  = w2;
        *(float4*)&Vs[li][lg + 12] = w3;
        __syncthreads();

#pragma unroll 2
        for (int kk = 0; kk < 64; kk++) {
            float pa[4];
#pragma unroll
            for (int r = 0; r < 4; r++) pa[r] = Ps[kk][(ty << 2) + r];
            float4 vb = *(const float4*)&Vs[kk][tx << 2];
            float vbv[4] = {vb.x, vb.y, vb.z, vb.w};
#pragma unroll
            for (int r = 0; r < 4; r++)
#pragma unroll
                for (int c = 0; c < 4; c++)
                    acc[r][c] += pa[r] * vbv[c];
        }
    }

#pragma unroll
    for (int r = 0; r < 4; r++) {
        int i = i0 + (ty << 2) + r;
        float sc = as_[(ty << 2) + r];
        float4 o = make_float4(acc[r][0]*sc, acc[r][1]*sc, acc[r][2]*sc, acc[r][3]*sc);
        *(float4*)&ctx[(size_t)i * EMB + h * HD + (tx << 2)] = o;
    }
}

// ---------------- LayerNorm --------------------------------------------------
__global__ __launch_bounds__(256) void ln_kernel(
    const float* __restrict__ y, const float* __restrict__ gam,
    const float* __restrict__ bet, float* __restrict__ out)
{
    int row = blockIdx.x;
    const float* yr = y + (size_t)row * EMB;
    int t = threadIdx.x;
    float v0 = yr[t], v1 = yr[t + 256], v2 = yr[t + 512];

    __shared__ float red[8];
    int lane = t & 31, w = t >> 5;

    float s = v0 + v1 + v2;
#pragma unroll
    for (int o = 16; o; o >>= 1) s += __shfl_xor_sync(0xffffffffu, s, o);
    if (lane == 0) red[w] = s;
    __syncthreads();
    float tot = red[0] + red[1] + red[2] + red[3] + red[4] + red[5] + red[6] + red[7];
    float mean = tot * (1.0f / EMB);

    float d0 = v0 - mean, d1 = v1 - mean, d2 = v2 - mean;
    float sq = d0 * d0 + d1 * d1 + d2 * d2;
    __syncthreads();
#pragma unroll
    for (int o = 16; o; o >>= 1) sq += __shfl_xor_sync(0xffffffffu, sq, o);
    if (lane == 0) red[w] = sq;
    __syncthreads();
    float var = (red[0]+red[1]+red[2]+red[3]+red[4]+red[5]+red[6]+red[7]) * (1.0f / EMB);
    float inv = rsqrtf(var + 1e-12f);

    float* outr = out + (size_t)row * EMB;
    outr[t]       = gam[t]       * d0 * inv + bet[t];
    outr[t + 256] = gam[t + 256] * d1 * inv + bet[t + 256];
    outr[t + 512] = gam[t + 512] * d2 * inv + bet[t + 512];
}

// ---------------- launch -----------------------------------------------------
extern "C" void kernel_launch(void* const* d_in, const int* in_sizes, int n_in,
                              void* d_out, int out_size)
{
    const float* X  = (const float*)d_in[0];
    const float* Wq = (const float*)d_in[1];
    const float* bq = (const float*)d_in[2];
    const float* Wk = (const float*)d_in[3];
    const float* bk = (const float*)d_in[4];
    const float* Wv = (const float*)d_in[5];
    const float* bv = (const float*)d_in[6];
    const float* Wo = (const float*)d_in[7];
    const float* bo = (const float*)d_in[8];
    const float* lg = (const float*)d_in[9];
    const float* lb = (const float*)d_in[10];
    float* out = (float*)d_out;

    void *pQ, *pK, *pV, *pa, *pb, *pr, *pctx, *py;
    cudaGetSymbolAddress(&pQ, g_Q);
    cudaGetSymbolAddress(&pK, g_K);
    cudaGetSymbolAddress(&pV, g_V);
    cudaGetSymbolAddress(&pa, g_a);
    cudaGetSymbolAddress(&pb, g_b);
    cudaGetSymbolAddress(&pr, g_r);
    cudaGetSymbolAddress(&pctx, g_ctx);
    cudaGetSymbolAddress(&py, g_y);

    float* fa = (float*)pa;
    float* fb = (float*)pb;
    float* fr = (float*)pr;

    dim3 gProj(EMB / 128, SEQ / 128);   // (6,16)

    zero_kernel<<<NH * SEQ / 256, 256>>>(fr);

    sgemm128<<<gProj, 256>>>(X, Wq, bq, nullptr, (float*)pQ, SEQ, EMB, EMB);
    sgemm128<<<gProj, 256>>>(X, Wk, bk, nullptr, (float*)pK, SEQ, EMB, EMB);
    sgemm128<<<gProj, 256>>>(X, Wv, bv, nullptr, (float*)pV, SEQ, EMB, EMB);

    qk_exp_kernel<<<dim3(SEQ / 128, SEQ / 128, NH), 256>>>((float*)pQ, (float*)pK);

    // Sinkhorn: 3 iterations (first row pass fused into qk_exp row sums)
    fin_kernel<<<NH * SEQ / 256, 256>>>(fa, fr);                       // a1
    colmv_kernel<<<dim3(SEQ / 128, 8, NH), 128>>>(fa, fr);
    fin_kernel<<<NH * SEQ / 256, 256>>>(fb, fr);                       // b1
    rowmv_kernel<<<dim3(SEQ / 16, NH), 256>>>(fb, fa);                 // a2
    colmv_kernel<<<dim3(SEQ / 128, 8, NH), 128>>>(fa, fr);
    fin_kernel<<<NH * SEQ / 256, 256>>>(fb, fr);                       // b2
    rowmv_kernel<<<dim3(SEQ / 16, NH), 256>>>(fb, fa);                 // a3
    colmv_kernel<<<dim3(SEQ / 128, 8, NH), 128>>>(fa, fr);
    fin_kernel<<<NH * SEQ / 256, 256>>>(fb, fr);                       // b3

    av_kernel<<<dim3(SEQ / 64, NH), 256>>>((float*)pV, fa, fb, (float*)pctx);

    sgemm128<<<gProj, 256>>>((float*)pctx, Wo, bo, X, (float*)py, SEQ, EMB, EMB);

    ln_kernel<<<SEQ, 256>>>((float*)py, lg, lb, out);
}

// round 3
// speedup vs baseline: 3.9935x; 3.9935x over previous
#include <cuda_runtime.h>
#include <cuda_bf16.h>
#include <cstdint>
#include <cstddef>

#define SEQ 2048
#define EMB 768
#define NH  12
#define HD  64
#define MU_F (1.0f/2048.0f)
#define PADK 40   // padded K-stride (elements) for SMEM tiles

// ---------------- scratch (device globals; no allocation allowed) -------------
__device__ __nv_bfloat16 g_Xb[SEQ*EMB];
__device__ __nv_bfloat16 g_Wt[4*EMB*EMB];           // Wq,Wk,Wv,Wo transposed [n][k]
__device__ __nv_bfloat16 g_QKV[3*SEQ*EMB];          // Q(=q/8), K, V  bf16
__device__ __nv_bfloat16 g_E[(size_t)NH*SEQ*SEQ];   // exp(QK^T/8) bf16 (100.7MB)
__device__ __nv_bfloat16 g_Vt[NH*HD*SEQ];           // (diag(b) V)^T per head
__device__ __nv_bfloat16 g_ctxb[SEQ*EMB];
__device__ float g_a[NH*SEQ];
__device__ float g_b[NH*SEQ];
__device__ float g_r[NH*SEQ];
__device__ float g_y[SEQ*EMB];

// ============================ PTX helpers =====================================
__device__ __forceinline__ uint32_t smem_u32(const void* p) {
    uint32_t a;
    asm("{ .reg .u64 t; cvta.to.shared.u64 t, %1; cvt.u32.u64 %0, t; }"
        : "=r"(a) : "l"(p));
    return a;
}
__device__ __forceinline__ void cpa16(uint32_t dst, const void* src) {
    asm volatile("cp.async.cg.shared.global [%0], [%1], 16;" :: "r"(dst), "l"(src));
}
#define CP_COMMIT() asm volatile("cp.async.commit_group;" ::: "memory")
#define CP_WAIT1()  asm volatile("cp.async.wait_group 1;" ::: "memory")
#define CP_WAIT0()  asm volatile("cp.async.wait_group 0;" ::: "memory")

__device__ __forceinline__ void ldsm4(uint32_t& r0, uint32_t& r1, uint32_t& r2,
                                      uint32_t& r3, uint32_t addr) {
    asm volatile("ldmatrix.sync.aligned.m8n8.x4.shared.b16 {%0,%1,%2,%3}, [%4];"
        : "=r"(r0), "=r"(r1), "=r"(r2), "=r"(r3) : "r"(addr));
}
__device__ __forceinline__ void mma16816(float* c, const uint32_t* a, const uint32_t* b) {
    asm volatile("mma.sync.aligned.m16n8k16.row.col.f32.bf16.bf16.f32 "
        "{%0,%1,%2,%3}, {%4,%5,%6,%7}, {%8,%9}, {%0,%1,%2,%3};"
        : "+f"(c[0]), "+f"(c[1]), "+f"(c[2]), "+f"(c[3])
        : "r"(a[0]), "r"(a[1]), "r"(a[2]), "r"(a[3]), "r"(b[0]), "r"(b[1]));
}

// ---------------- mma.sync block-GEMM core ------------------------------------
// C[128, BN] = A[128, K] * B[BN, K]^T ; A,B bf16 K-major. K in chunks of 32.
// 256 threads = 8 warps (4 M x 2 N); warp tile 32 x (BN/2).
// acc[mi][ni][4] per-thread fragments (mi: 2 m16 tiles, ni: BN/16 n8 tiles).
template<int BN>
__device__ __forceinline__ void gemm_core(
    const __nv_bfloat16* __restrict__ A, int lda,
    const __nv_bfloat16* __restrict__ B, int ldb,
    int nchunks, __nv_bfloat16* As, __nv_bfloat16* Bs,
    float acc[2][BN/16][4])
{
    constexpr int NF = BN / 16;                  // n8-frags per warp
    const int tid = threadIdx.x;
    const int lane = tid & 31, wid = tid >> 5;
    const int wm = wid >> 1, wn = wid & 1;
    const uint32_t asb = smem_u32(As), bsb = smem_u32(Bs);
    const uint32_t ASTG = 128 * PADK * 2, BSTG = BN * PADK * 2;

    // load addressing: 16B segs; A: 512 segs (2/thread), B: BN*4 segs
    const int lr = tid >> 2, lc = (tid & 3) * 8;
    const uint32_t adst = (uint32_t)(lr * PADK + lc) * 2;
    const uint32_t bdst = adst;

    // ldmatrix addressing (byte offsets, stage 0)
    uint32_t aoff[2], boff[NF / 2];
#pragma unroll
    for (int mi = 0; mi < 2; mi++) {
        int r = wm * 32 + mi * 16 + (lane & 15);
        int c = (lane >> 4) * 8;
        aoff[mi] = (uint32_t)(r * PADK + c) * 2;
    }
#pragma unroll
    for (int n2 = 0; n2 < NF / 2; n2++) {
        int g = lane >> 3;
        int r = wn * (BN / 2) + n2 * 16 + ((g >> 1) << 3) + (lane & 7);
        int c = (g & 1) * 8;
        boff[n2] = (uint32_t)(r * PADK + c) * 2;
    }

#pragma unroll
    for (int mi = 0; mi < 2; mi++)
#pragma unroll
        for (int ni = 0; ni < NF; ni++)
#pragma unroll
            for (int q = 0; q < 4; q++) acc[mi][ni][q] = 0.f;

    // preload chunk 0
    {
        const __nv_bfloat16* Ac = A;
        const __nv_bfloat16* Bc = B;
        cpa16(asb + adst, Ac + (size_t)lr * lda + lc);
        cpa16(asb + adst + 64u * PADK * 2, Ac + (size_t)(lr + 64) * lda + lc);
        cpa16(bsb + bdst, Bc + (size_t)lr * ldb + lc);
        if (BN == 128)
            cpa16(bsb + bdst + 64u * PADK * 2, Bc + (size_t)(lr + 64) * ldb + lc);
        CP_COMMIT();
    }

    for (int c = 0; c < nchunks; c++) {
        int s = c & 1;
        if (c + 1 < nchunks) {
            const __nv_bfloat16* Ac = A + (c + 1) * 32;
            const __nv_bfloat16* Bc = B + (c + 1) * 32;
            uint32_t ad = asb + (s ^ 1) * ASTG, bd = bsb + (s ^ 1) * BSTG;
            cpa16(ad + adst, Ac + (size_t)lr * lda + lc);
            cpa16(ad + adst + 64u * PADK * 2, Ac + (size_t)(lr + 64) * lda + lc);
            cpa16(bd + bdst, Bc + (size_t)lr * ldb + lc);
            if (BN == 128)
                cpa16(bd + bdst + 64u * PADK * 2, Bc + (size_t)(lr + 64) * ldb + lc);
            CP_COMMIT();
            CP_WAIT1();
        } else {
            CP_WAIT0();
        }
        __syncthreads();

        uint32_t ab = asb + s * ASTG, bb = bsb + s * BSTG;
#pragma unroll
        for (int ks = 0; ks < 2; ks++) {
            uint32_t af[2][4];
            ldsm4(af[0][0], af[0][1], af[0][2], af[0][3], ab + aoff[0] + ks * 32);
            ldsm4(af[1][0], af[1][1], af[1][2], af[1][3], ab + aoff[1] + ks * 32);
#pragma unroll
            for (int n2 = 0; n2 < NF / 2; n2++) {
                uint32_t bf[4];
                ldsm4(bf[0], bf[1], bf[2], bf[3], bb + boff[n2] + ks * 32);
                mma16816(acc[0][2 * n2],     af[0], bf + 0);
                mma16816(acc[0][2 * n2 + 1], af[0], bf + 2);
                mma16816(acc[1][2 * n2],     af[1], bf + 0);
                mma16816(acc[1][2 * n2 + 1], af[1], bf + 2);
            }
        }
        __syncthreads();
    }
}

// ---------------- prep kernels ------------------------------------------------
__global__ __launch_bounds__(256) void cvt_kernel(const float* __restrict__ X,
                                                  __nv_bfloat16* __restrict__ Xb) {
    int i = (blockIdx.x * 256 + threadIdx.x) * 4;
    float4 v = *(const float4*)(X + i);
    __nv_bfloat162 p0 = __floats2bfloat162_rn(v.x, v.y);
    __nv_bfloat162 p1 = __floats2bfloat162_rn(v.z, v.w);
    uint2 o = make_uint2(*(uint32_t*)&p0, *(uint32_t*)&p1);
    *(uint2*)(Xb + i) = o;
}

__global__ __launch_bounds__(256) void wtrans_kernel(
    const float* __restrict__ Wq, const float* __restrict__ Wk,
    const float* __restrict__ Wv, const float* __restrict__ Wo,
    __nv_bfloat16* __restrict__ Wt)
{
    int z = blockIdx.z;
    const float* W = (z == 0) ? Wq : (z == 1) ? Wk : (z == 2) ? Wv : Wo;
    __shared__ float t[32][33];
    int n0 = blockIdx.x * 32, k0 = blockIdx.y * 32;
    int tx = threadIdx.x & 31, ty = threadIdx.x >> 5;
#pragma unroll
    for (int r = 0; r < 4; r++)
        t[ty + r * 8][tx] = W[(size_t)(k0 + ty + r * 8) * EMB + n0 + tx];
    __syncthreads();
    __nv_bfloat16* O = Wt + (size_t)z * EMB * EMB;
#pragma unroll
    for (int r = 0; r < 4; r++)
        O[(size_t)(n0 + ty + r * 8) * EMB + k0 + tx] = __float2bfloat16(t[tx][ty + r * 8]);
}

// Vt[h][d][j] = V[j][h*64+d] * b[h][j]
__global__ __launch_bounds__(256) void vt_prep_kernel(
    const __nv_bfloat16* __restrict__ Vb, const float* __restrict__ bvec,
    __nv_bfloat16* __restrict__ Vt)
{
    int h = blockIdx.y, j0 = blockIdx.x * 64;
    __shared__ float t[64][65];
    int tid = threadIdx.x;
    int jj = tid >> 2, d0 = (tid & 3) * 16;
    const __nv_bfloat16* src = Vb + (size_t)(j0 + jj) * EMB + h * HD + d0;
    __nv_bfloat16 tmp[16];
    *(uint4*)tmp = *(const uint4*)src;
    *(uint4*)(tmp + 8) = *(const uint4*)(src + 8);
#pragma unroll
    for (int q = 0; q < 16; q++) t[jj][d0 + q] = __bfloat162float(tmp[q]);
    __syncthreads();
    int dd = tid >> 2, jb = (tid & 3) * 16;
    __nv_bfloat16 o[16];
#pragma unroll
    for (int q = 0; q < 16; q++) {
        int j = j0 + jb + q;
        o[q] = __float2bfloat16(t[jb + q][dd] * bvec[h * SEQ + j]);
    }
    __nv_bfloat16* dst = Vt + ((size_t)h * HD + dd) * SEQ + j0 + jb;
    *(uint4*)dst = *(uint4*)o;
    *(uint4*)(dst + 8) = *(uint4*)(o + 8);
}

// ---------------- QKV projection ----------------------------------------------
__global__ __launch_bounds__(256) void proj_kernel(
    const __nv_bfloat16* __restrict__ Xb, const __nv_bfloat16* __restrict__ Wt,
    const float* __restrict__ bq, const float* __restrict__ bk,
    const float* __restrict__ bv, __nv_bfloat16* __restrict__ Out)
{
    __shared__ __align__(16) __nv_bfloat16 As[2][128 * PADK];
    __shared__ __align__(16) __nv_bfloat16 Bs[2][128 * PADK];
    int z = blockIdx.z;
    int n0 = blockIdx.x * 128, i0 = blockIdx.y * 128;
    const float* bias = (z == 0) ? bq : (z == 1) ? bk : bv;
    float scale = (z == 0) ? 0.125f : 1.0f;

    float acc[2][8][4];
    gemm_core<128>(Xb + (size_t)i0 * EMB, EMB,
                   Wt + (size_t)z * EMB * EMB + (size_t)n0 * EMB, EMB,
                   EMB / 32, As[0], Bs[0], acc);

    int lane = threadIdx.x & 31, wid = threadIdx.x >> 5;
    int wm = wid >> 1, wn = wid & 1;
    int r0 = wm * 32 + (lane >> 2), cb = wn * 64 + (lane & 3) * 2;
    __nv_bfloat16* O = Out + (size_t)z * SEQ * EMB;
#pragma unroll
    for (int mi = 0; mi < 2; mi++)
#pragma unroll
        for (int m8 = 0; m8 < 2; m8++) {
            int row = i0 + r0 + mi * 16 + m8 * 8;
#pragma unroll
            for (int ni = 0; ni < 8; ni++) {
                int col = n0 + cb + ni * 8;
                float f0 = (acc[mi][ni][m8 * 2 + 0] + bias[col])     * scale;
                float f1 = (acc[mi][ni][m8 * 2 + 1] + bias[col + 1]) * scale;
                __nv_bfloat162 p = __floats2bfloat162_rn(f0, f1);
                *(uint32_t*)(O + (size_t)row * EMB + col) = *(uint32_t*)&p;
            }
        }
}

// ---------------- E = exp(QK^T/8) + row sums -----------------------------------
__global__ __launch_bounds__(256) void qk_kernel(
    const __nv_bfloat16* __restrict__ QKV, float* __restrict__ rsumg)
{
    __shared__ __align__(16) __nv_bfloat16 As[2][128 * PADK];
    __shared__ __align__(16) __nv_bfloat16 Bs[2][128 * PADK];
    __shared__ float rsum[128];
    int j0 = blockIdx.x * 128, i0 = blockIdx.y * 128, h = blockIdx.z;
    if (threadIdx.x < 128) rsum[threadIdx.x] = 0.f;

    float acc[2][8][4];
    gemm_core<128>(QKV + (size_t)i0 * EMB + h * HD, EMB,
                   QKV + (size_t)SEQ * EMB + (size_t)j0 * EMB + h * HD, EMB,
                   HD / 32, As[0], Bs[0], acc);

    int lane = threadIdx.x & 31, wid = threadIdx.x >> 5;
    int wm = wid >> 1, wn = wid & 1;
    int r0 = wm * 32 + (lane >> 2), cb = wn * 64 + (lane & 3) * 2;
#pragma unroll
    for (int mi = 0; mi < 2; mi++)
#pragma unroll
        for (int m8 = 0; m8 < 2; m8++) {
            int lrow = r0 + mi * 16 + m8 * 8;
            int row = i0 + lrow;
            __nv_bfloat16* O = g_E + ((size_t)h * SEQ + row) * SEQ + j0;
            float rs = 0.f;
#pragma unroll
            for (int ni = 0; ni < 8; ni++) {
                float e0 = __expf(acc[mi][ni][m8 * 2 + 0]);
                float e1 = __expf(acc[mi][ni][m8 * 2 + 1]);
                rs += e0 + e1;
                __nv_bfloat162 p = __floats2bfloat162_rn(e0, e1);
                *(uint32_t*)(O + cb + ni * 8) = *(uint32_t*)&p;
            }
            rs += __shfl_xor_sync(0xffffffffu, rs, 1);
            rs += __shfl_xor_sync(0xffffffffu, rs, 2);
            if ((lane & 3) == 0) atomicAdd(&rsum[lrow], rs);
        }
    __syncthreads();
    if (threadIdx.x < 128)
        atomicAdd(&rsumg[h * SEQ + i0 + threadIdx.x], rsum[threadIdx.x]);
}

// ---------------- ctx = n * diag(a) * E * (diag(b) V) --------------------------
__global__ __launch_bounds__(256) void av_kernel(
    const __nv_bfloat16* __restrict__ Vt, const float* __restrict__ avec,
    __nv_bfloat16* __restrict__ ctx)
{
    __shared__ __align__(16) __nv_bfloat16 As[2][128 * PADK];
    __shared__ __align__(16) __nv_bfloat16 Bs[2][64 * PADK];
    int i0 = blockIdx.x * 128, h = blockIdx.y;

    float acc[2][4][4];
    gemm_core<64>(g_E + (size_t)h * SEQ * SEQ + (size_t)i0 * SEQ, SEQ,
                  Vt + (size_t)h * HD * SEQ, SEQ,
                  SEQ / 32, As[0], Bs[0], acc);

    int lane = threadIdx.x & 31, wid = threadIdx.x >> 5;
    int wm = wid >> 1, wn = wid & 1;
    int r0 = wm * 32 + (lane >> 2), cb = wn * 32 + (lane & 3) * 2;
#pragma unroll
    for (int mi = 0; mi < 2; mi++)
#pragma unroll
        for (int m8 = 0; m8 < 2; m8++) {
            int row = i0 + r0 + mi * 16 + m8 * 8;
            float sc = avec[h * SEQ + row] * 2048.0f;
            __nv_bfloat16* O = ctx + (size_t)row * EMB + h * HD;
#pragma unroll
            for (int ni = 0; ni < 4; ni++) {
                float f0 = acc[mi][ni][m8 * 2 + 0] * sc;
                float f1 = acc[mi][ni][m8 * 2 + 1] * sc;
                __nv_bfloat162 p = __floats2bfloat162_rn(f0, f1);
                *(uint32_t*)(O + cb + ni * 8) = *(uint32_t*)&p;
            }
        }
}

// ---------------- y = ctx @ Wo + bo + X ----------------------------------------
__global__ __launch_bounds__(256) void final_kernel(
    const __nv_bfloat16* __restrict__ ctx, const __nv_bfloat16* __restrict__ Wt,
    const float* __restrict__ bo, const float* __restrict__ X,
    float* __restrict__ Y)
{
    __shared__ __align__(16) __nv_bfloat16 As[2][128 * PADK];
    __shared__ __align__(16) __nv_bfloat16 Bs[2][128 * PADK];
    int n0 = blockIdx.x * 128, i0 = blockIdx.y * 128;

    float acc[2][8][4];
    gemm_core<128>(ctx + (size_t)i0 * EMB, EMB,
                   Wt + (size_t)3 * EMB * EMB + (size_t)n0 * EMB, EMB,
                   EMB / 32, As[0], Bs[0], acc);

    int lane = threadIdx.x & 31, wid = threadIdx.x >> 5;
    int wm = wid >> 1, wn = wid & 1;
    int r0 = wm * 32 + (lane >> 2), cb = wn * 64 + (lane & 3) * 2;
#pragma unroll
    for (int mi = 0; mi < 2; mi++)
#pragma unroll
        for (int m8 = 0; m8 < 2; m8++) {
            int row = i0 + r0 + mi * 16 + m8 * 8;
#pragma unroll
            for (int ni = 0; ni < 8; ni++) {
                int col = n0 + cb + ni * 8;
                float2 xv = *(const float2*)(X + (size_t)row * EMB + col);
                float2 o;
                o.x = acc[mi][ni][m8 * 2 + 0] + bo[col]     + xv.x;
                o.y = acc[mi][ni][m8 * 2 + 1] + bo[col + 1] + xv.y;
                *(float2*)(Y + (size_t)row * EMB + col) = o;
            }
        }
}

// ---------------- Sinkhorn vector kernels --------------------------------------
__global__ __launch_bounds__(256) void rowmv_kernel(
    const float* __restrict__ bvec, float* __restrict__ avec)
{
    int h = blockIdx.y;
    __shared__ float bs[SEQ];
    for (int j = threadIdx.x; j < SEQ; j += 256) bs[j] = bvec[h * SEQ + j];
    __syncthreads();
    int w = threadIdx.x >> 5, lane = threadIdx.x & 31;
#pragma unroll
    for (int rr = 0; rr < 2; rr++) {
        int row = blockIdx.x * 16 + w * 2 + rr;
        const uint4* Ep4 = (const uint4*)(g_E + ((size_t)h * SEQ + row) * SEQ);
        float sum = 0.f;
#pragma unroll 2
        for (int it = lane; it < SEQ / 8; it += 32) {
            uint4 u = Ep4[it];
            __nv_bfloat162 e2[4];
            *(uint4*)e2 = u;
            int base = it * 8;
#pragma unroll
            for (int q = 0; q < 4; q++) {
                float2 f = __bfloat1622float2(e2[q]);
                sum += f.x * bs[base + 2 * q] + f.y * bs[base + 2 * q + 1];
            }
        }
#pragma unroll
        for (int o = 16; o; o >>= 1) sum += __shfl_xor_sync(0xffffffffu, sum, o);
        if (lane == 0) avec[h * SEQ + row] = MU_F / sum;
    }
}

__global__ __launch_bounds__(128) void colmv_kernel(
    const float* __restrict__ avec, float* __restrict__ cvec)
{
    int h = blockIdx.z;
    int j = blockIdx.x * 128 + threadIdx.x;
    int i0 = blockIdx.y * (SEQ / 8);
    __shared__ float as_[SEQ / 8];
    for (int i = threadIdx.x; i < SEQ / 8; i += 128) as_[i] = avec[h * SEQ + i0 + i];
    __syncthreads();
    const __nv_bfloat16* Ep = g_E + (size_t)h * SEQ * SEQ + (size_t)i0 * SEQ + j;
    float sum = 0.f;
#pragma unroll 8
    for (int i = 0; i < SEQ / 8; i++)
        sum += __bfloat162float(Ep[(size_t)i * SEQ]) * as_[i];
    atomicAdd(&cvec[h * SEQ + j], sum);
}

__global__ void fin_kernel(float* __restrict__ dst, float* __restrict__ r)
{
    int i = blockIdx.x * 256 + threadIdx.x;
    float c = r[i];
    r[i] = 0.f;
    dst[i] = MU_F / c;
}

__global__ void zero_kernel(float* __restrict__ r)
{
    r[blockIdx.x * 256 + threadIdx.x] = 0.f;
}

// ---------------- LayerNorm ---------------------------------------------------
__global__ __launch_bounds__(256) void ln_kernel(
    const float* __restrict__ y, const float* __restrict__ gam,
    const float* __restrict__ bet, float* __restrict__ out)
{
    int row = blockIdx.x;
    const float* yr = y + (size_t)row * EMB;
    int t = threadIdx.x;
    float v0 = yr[t], v1 = yr[t + 256], v2 = yr[t + 512];

    __shared__ float red[8];
    int lane = t & 31, w = t >> 5;

    float s = v0 + v1 + v2;
#pragma unroll
    for (int o = 16; o; o >>= 1) s += __shfl_xor_sync(0xffffffffu, s, o);
    if (lane == 0) red[w] = s;
    __syncthreads();
    float tot = red[0] + red[1] + red[2] + red[3] + red[4] + red[5] + red[6] + red[7];
    float mean = tot * (1.0f / EMB);

    float d0 = v0 - mean, d1 = v1 - mean, d2 = v2 - mean;
    float sq = d0 * d0 + d1 * d1 + d2 * d2;
    __syncthreads();
#pragma unroll
    for (int o = 16; o; o >>= 1) sq += __shfl_xor_sync(0xffffffffu, sq, o);
    if (lane == 0) red[w] = sq;
    __syncthreads();
    float var = (red[0]+red[1]+red[2]+red[3]+red[4]+red[5]+red[6]+red[7]) * (1.0f / EMB);
    float inv = rsqrtf(var + 1e-12f);

    float* outr = out + (size_t)row * EMB;
    outr[t]       = gam[t]       * d0 * inv + bet[t];
    outr[t + 256] = gam[t + 256] * d1 * inv + bet[t + 256];
    outr[t + 512] = gam[t + 512] * d2 * inv + bet[t + 512];
}

// ---------------- launch ------------------------------------------------------
extern "C" void kernel_launch(void* const* d_in, const int* in_sizes, int n_in,
                              void* d_out, int out_size)
{
    const float* X  = (const float*)d_in[0];
    const float* Wq = (const float*)d_in[1];
    const float* bq = (const float*)d_in[2];
    const float* Wk = (const float*)d_in[3];
    const float* bk = (const float*)d_in[4];
    const float* Wv = (const float*)d_in[5];
    const float* bv = (const float*)d_in[6];
    const float* Wo = (const float*)d_in[7];
    const float* bo = (const float*)d_in[8];
    const float* lg = (const float*)d_in[9];
    const float* lb = (const float*)d_in[10];
    float* out = (float*)d_out;

    void *pXb, *pWt, *pQKV, *pVt, *pctx, *pa, *pb, *pr, *py;
    cudaGetSymbolAddress(&pXb, g_Xb);
    cudaGetSymbolAddress(&pWt, g_Wt);
    cudaGetSymbolAddress(&pQKV, g_QKV);
    cudaGetSymbolAddress(&pVt, g_Vt);
    cudaGetSymbolAddress(&pctx, g_ctxb);
    cudaGetSymbolAddress(&pa, g_a);
    cudaGetSymbolAddress(&pb, g_b);
    cudaGetSymbolAddress(&pr, g_r);
    cudaGetSymbolAddress(&py, g_y);

    __nv_bfloat16* Xb  = (__nv_bfloat16*)pXb;
    __nv_bfloat16* Wt  = (__nv_bfloat16*)pWt;
    __nv_bfloat16* QKV = (__nv_bfloat16*)pQKV;
    __nv_bfloat16* Vt  = (__nv_bfloat16*)pVt;
    __nv_bfloat16* ctx = (__nv_bfloat16*)pctx;
    float* fa = (float*)pa;
    float* fb = (float*)pb;
    float* fr = (float*)pr;
    float* fy = (float*)py;

    zero_kernel<<<NH * SEQ / 256, 256>>>(fr);

    cvt_kernel<<<SEQ * EMB / 1024, 256>>>(X, Xb);
    wtrans_kernel<<<dim3(EMB / 32, EMB / 32, 4), 256>>>(Wq, Wk, Wv, Wo, Wt);

    proj_kernel<<<dim3(EMB / 128, SEQ / 128, 3), 256>>>(Xb, Wt, bq, bk, bv, QKV);

    qk_kernel<<<dim3(SEQ / 128, SEQ / 128, NH), 256>>>(QKV, fr);

    // Sinkhorn: 3 iterations (first row pass fused into qk row sums)
    fin_kernel<<<NH * SEQ / 256, 256>>>(fa, fr);                       // a1
    colmv_kernel<<<dim3(SEQ / 128, 8, NH), 128>>>(fa, fr);
    fin_kernel<<<NH * SEQ / 256, 256>>>(fb, fr);                       // b1
    rowmv_kernel<<<dim3(SEQ / 16, NH), 256>>>(fb, fa);                 // a2
    colmv_kernel<<<dim3(SEQ / 128, 8, NH), 128>>>(fa, fr);
    fin_kernel<<<NH * SEQ / 256, 256>>>(fb, fr);                       // b2
    rowmv_kernel<<<dim3(SEQ / 16, NH), 256>>>(fb, fa);                 // a3
    colmv_kernel<<<dim3(SEQ / 128, 8, NH), 128>>>(fa, fr);
    fin_kernel<<<NH * SEQ / 256, 256>>>(fb, fr);                       // b3

    vt_prep_kernel<<<dim3(SEQ / 64, NH), 256>>>(QKV + (size_t)2 * SEQ * EMB, fb, Vt);

    av_kernel<<<dim3(SEQ / 128, NH), 256>>>(Vt, fa, ctx);

    final_kernel<<<dim3(EMB / 128, SEQ / 128), 256>>>(ctx, Wt, bo, X, fy);

    ln_kernel<<<SEQ, 256>>>(fy, lg, lb, out);
}

// round 4
// speedup vs baseline: 4.2345x; 1.0603x over previous
#include <cuda_runtime.h>
#include <cuda_bf16.h>
#include <cuda_fp16.h>
#include <cstdint>
#include <cstddef>

#define SEQ 2048
#define EMB 768
#define NH  12
#define HD  64
#define MU_F (1.0f/2048.0f)
#define PADK 40   // padded K-stride (elements) for SMEM tiles

// ---------------- scratch (device globals; no allocation allowed) -------------
__device__ __nv_bfloat16 g_Xb[SEQ*EMB];
__device__ __nv_bfloat16 g_Wt[4*EMB*EMB];           // Wq,Wk,Wv,Wo transposed [n][k]
__device__ __nv_bfloat16 g_QKV[3*SEQ*EMB];          // Q(=q/8), K, V  bf16
__device__ unsigned char g_E8[(size_t)NH*SEQ*SEQ];  // exp(QK^T/8) e4m3 (50.3MB, L2-resident)
__device__ __half g_Vt[NH*HD*SEQ];                  // (diag(b) V)^T per head, f16
__device__ __nv_bfloat16 g_ctxb[SEQ*EMB];
__device__ float g_a[NH*SEQ];
__device__ float g_b[NH*SEQ];
__device__ float g_r[NH*SEQ];
__device__ float g_y[SEQ*EMB];

// ============================ PTX helpers =====================================
__device__ __forceinline__ uint32_t smem_u32(const void* p) {
    uint32_t a;
    asm("{ .reg .u64 t; cvta.to.shared.u64 t, %1; cvt.u32.u64 %0, t; }"
        : "=r"(a) : "l"(p));
    return a;
}
__device__ __forceinline__ void cpa16(uint32_t dst, const void* src) {
    asm volatile("cp.async.cg.shared.global [%0], [%1], 16;" :: "r"(dst), "l"(src));
}
#define CP_COMMIT() asm volatile("cp.async.commit_group;" ::: "memory")
#define CP_WAIT1()  asm volatile("cp.async.wait_group 1;" ::: "memory")
#define CP_WAIT0()  asm volatile("cp.async.wait_group 0;" ::: "memory")

__device__ __forceinline__ void ldsm4(uint32_t& r0, uint32_t& r1, uint32_t& r2,
                                      uint32_t& r3, uint32_t addr) {
    asm volatile("ldmatrix.sync.aligned.m8n8.x4.shared.b16 {%0,%1,%2,%3}, [%4];"
        : "=r"(r0), "=r"(r1), "=r"(r2), "=r"(r3) : "r"(addr));
}
__device__ __forceinline__ void mma16816(float* c, const uint32_t* a, const uint32_t* b) {
    asm volatile("mma.sync.aligned.m16n8k16.row.col.f32.bf16.bf16.f32 "
        "{%0,%1,%2,%3}, {%4,%5,%6,%7}, {%8,%9}, {%0,%1,%2,%3};"
        : "+f"(c[0]), "+f"(c[1]), "+f"(c[2]), "+f"(c[3])
        : "r"(a[0]), "r"(a[1]), "r"(a[2]), "r"(a[3]), "r"(b[0]), "r"(b[1]));
}
__device__ __forceinline__ void mma16816h(float* c, const uint32_t* a, const uint32_t* b) {
    asm volatile("mma.sync.aligned.m16n8k16.row.col.f32.f16.f16.f32 "
        "{%0,%1,%2,%3}, {%4,%5,%6,%7}, {%8,%9}, {%0,%1,%2,%3};"
        : "+f"(c[0]), "+f"(c[1]), "+f"(c[2]), "+f"(c[3])
        : "r"(a[0]), "r"(a[1]), "r"(a[2]), "r"(a[3]), "r"(b[0]), "r"(b[1]));
}

// fp8 e4m3 pack/unpack
__device__ __forceinline__ uint16_t pk_e4m3(float lo, float hi) {
    uint16_t r;
    asm("cvt.rn.satfinite.e4m3x2.f32 %0, %1, %2;" : "=h"(r) : "f"(hi), "f"(lo));
    return r;
}
__device__ __forceinline__ void dec4(uint32_t w, float2& lo, float2& hi) {
    uint32_t f0, f1;
    asm("cvt.rn.f16x2.e4m3x2 %0, %1;" : "=r"(f0) : "h"((uint16_t)(w & 0xffffu)));
    asm("cvt.rn.f16x2.e4m3x2 %0, %1;" : "=r"(f1) : "h"((uint16_t)(w >> 16)));
    lo = __half22float2(*(__half2*)&f0);
    hi = __half22float2(*(__half2*)&f1);
}

// ---------------- mma.sync block-GEMM core (bf16) ------------------------------
template<int BN>
__device__ __forceinline__ void gemm_core(
    const __nv_bfloat16* __restrict__ A, int lda,
    const __nv_bfloat16* __restrict__ B, int ldb,
    int nchunks, __nv_bfloat16* As, __nv_bfloat16* Bs,
    float acc[2][BN/16][4])
{
    constexpr int NF = BN / 16;
    const int tid = threadIdx.x;
    const int lane = tid & 31, wid = tid >> 5;
    const int wm = wid >> 1, wn = wid & 1;
    const uint32_t asb = smem_u32(As), bsb = smem_u32(Bs);
    const uint32_t ASTG = 128 * PADK * 2, BSTG = BN * PADK * 2;

    const int lr = tid >> 2, lc = (tid & 3) * 8;
    const uint32_t adst = (uint32_t)(lr * PADK + lc) * 2;
    const uint32_t bdst = adst;

    uint32_t aoff[2], boff[NF / 2];
#pragma unroll
    for (int mi = 0; mi < 2; mi++) {
        int r = wm * 32 + mi * 16 + (lane & 15);
        int c = (lane >> 4) * 8;
        aoff[mi] = (uint32_t)(r * PADK + c) * 2;
    }
#pragma unroll
    for (int n2 = 0; n2 < NF / 2; n2++) {
        int g = lane >> 3;
        int r = wn * (BN / 2) + n2 * 16 + ((g >> 1) << 3) + (lane & 7);
        int c = (g & 1) * 8;
        boff[n2] = (uint32_t)(r * PADK + c) * 2;
    }

#pragma unroll
    for (int mi = 0; mi < 2; mi++)
#pragma unroll
        for (int ni = 0; ni < NF; ni++)
#pragma unroll
            for (int q = 0; q < 4; q++) acc[mi][ni][q] = 0.f;

    {
        cpa16(asb + adst, A + (size_t)lr * lda + lc);
        cpa16(asb + adst + 64u * PADK * 2, A + (size_t)(lr + 64) * lda + lc);
        cpa16(bsb + bdst, B + (size_t)lr * ldb + lc);
        if (BN == 128)
            cpa16(bsb + bdst + 64u * PADK * 2, B + (size_t)(lr + 64) * ldb + lc);
        CP_COMMIT();
    }

    for (int c = 0; c < nchunks; c++) {
        int s = c & 1;
        if (c + 1 < nchunks) {
            const __nv_bfloat16* Ac = A + (c + 1) * 32;
            const __nv_bfloat16* Bc = B + (c + 1) * 32;
            uint32_t ad = asb + (s ^ 1) * ASTG, bd = bsb + (s ^ 1) * BSTG;
            cpa16(ad + adst, Ac + (size_t)lr * lda + lc);
            cpa16(ad + adst + 64u * PADK * 2, Ac + (size_t)(lr + 64) * lda + lc);
            cpa16(bd + bdst, Bc + (size_t)lr * ldb + lc);
            if (BN == 128)
                cpa16(bd + bdst + 64u * PADK * 2, Bc + (size_t)(lr + 64) * ldb + lc);
            CP_COMMIT();
            CP_WAIT1();
        } else {
            CP_WAIT0();
        }
        __syncthreads();

        uint32_t ab = asb + s * ASTG, bb = bsb + s * BSTG;
#pragma unroll
        for (int ks = 0; ks < 2; ks++) {
            uint32_t af[2][4];
            ldsm4(af[0][0], af[0][1], af[0][2], af[0][3], ab + aoff[0] + ks * 32);
            ldsm4(af[1][0], af[1][1], af[1][2], af[1][3], ab + aoff[1] + ks * 32);
#pragma unroll
            for (int n2 = 0; n2 < NF / 2; n2++) {
                uint32_t bf[4];
                ldsm4(bf[0], bf[1], bf[2], bf[3], bb + boff[n2] + ks * 32);
                mma16816(acc[0][2 * n2],     af[0], bf + 0);
                mma16816(acc[0][2 * n2 + 1], af[0], bf + 2);
                mma16816(acc[1][2 * n2],     af[1], bf + 0);
                mma16816(acc[1][2 * n2 + 1], af[1], bf + 2);
            }
        }
        __syncthreads();
    }
}

// ---------------- prep kernels ------------------------------------------------
__global__ __launch_bounds__(256) void cvt_kernel(const float* __restrict__ X,
                                                  __nv_bfloat16* __restrict__ Xb) {
    int i = (blockIdx.x * 256 + threadIdx.x) * 4;
    float4 v = *(const float4*)(X + i);
    __nv_bfloat162 p0 = __floats2bfloat162_rn(v.x, v.y);
    __nv_bfloat162 p1 = __floats2bfloat162_rn(v.z, v.w);
    uint2 o = make_uint2(*(uint32_t*)&p0, *(uint32_t*)&p1);
    *(uint2*)(Xb + i) = o;
}

__global__ __launch_bounds__(256) void wtrans_kernel(
    const float* __restrict__ Wq, const float* __restrict__ Wk,
    const float* __restrict__ Wv, const float* __restrict__ Wo,
    __nv_bfloat16* __restrict__ Wt)
{
    int z = blockIdx.z;
    const float* W = (z == 0) ? Wq : (z == 1) ? Wk : (z == 2) ? Wv : Wo;
    __shared__ float t[32][33];
    int n0 = blockIdx.x * 32, k0 = blockIdx.y * 32;
    int tx = threadIdx.x & 31, ty = threadIdx.x >> 5;
#pragma unroll
    for (int r = 0; r < 4; r++)
        t[ty + r * 8][tx] = W[(size_t)(k0 + ty + r * 8) * EMB + n0 + tx];
    __syncthreads();
    __nv_bfloat16* O = Wt + (size_t)z * EMB * EMB;
#pragma unroll
    for (int r = 0; r < 4; r++)
        O[(size_t)(n0 + ty + r * 8) * EMB + k0 + tx] = __float2bfloat16(t[tx][ty + r * 8]);
}

// Vt[h][d][j] = V[j][h*64+d] * b[h][j]   (f16)
__global__ __launch_bounds__(256) void vt_prep_kernel(
    const __nv_bfloat16* __restrict__ Vb, const float* __restrict__ bvec,
    __half* __restrict__ Vt)
{
    int h = blockIdx.y, j0 = blockIdx.x * 64;
    __shared__ float t[64][65];
    int tid = threadIdx.x;
    int jj = tid >> 2, d0 = (tid & 3) * 16;
    const __nv_bfloat16* src = Vb + (size_t)(j0 + jj) * EMB + h * HD + d0;
    __nv_bfloat16 tmp[16];
    *(uint4*)tmp = *(const uint4*)src;
    *(uint4*)(tmp + 8) = *(const uint4*)(src + 8);
#pragma unroll
    for (int q = 0; q < 16; q++) t[jj][d0 + q] = __bfloat162float(tmp[q]);
    __syncthreads();
    int dd = tid >> 2, jb = (tid & 3) * 16;
    __half o[16];
#pragma unroll
    for (int q = 0; q < 16; q++) {
        int j = j0 + jb + q;
        o[q] = __float2half(t[jb + q][dd] * bvec[h * SEQ + j]);
    }
    __half* dst = Vt + ((size_t)h * HD + dd) * SEQ + j0 + jb;
    *(uint4*)dst = *(uint4*)o;
    *(uint4*)(dst + 8) = *(uint4*)(o + 8);
}

// ---------------- QKV projection ----------------------------------------------
__global__ __launch_bounds__(256) void proj_kernel(
    const __nv_bfloat16* __restrict__ Xb, const __nv_bfloat16* __restrict__ Wt,
    const float* __restrict__ bq, const float* __restrict__ bk,
    const float* __restrict__ bv, __nv_bfloat16* __restrict__ Out)
{
    __shared__ __align__(16) __nv_bfloat16 As[2][128 * PADK];
    __shared__ __align__(16) __nv_bfloat16 Bs[2][128 * PADK];
    int z = blockIdx.z;
    int n0 = blockIdx.x * 128, i0 = blockIdx.y * 128;
    const float* bias = (z == 0) ? bq : (z == 1) ? bk : bv;
    float scale = (z == 0) ? 0.125f : 1.0f;

    float acc[2][8][4];
    gemm_core<128>(Xb + (size_t)i0 * EMB, EMB,
                   Wt + (size_t)z * EMB * EMB + (size_t)n0 * EMB, EMB,
                   EMB / 32, As[0], Bs[0], acc);

    int lane = threadIdx.x & 31, wid = threadIdx.x >> 5;
    int wm = wid >> 1, wn = wid & 1;
    int r0 = wm * 32 + (lane >> 2), cb = wn * 64 + (lane & 3) * 2;
    __nv_bfloat16* O = Out + (size_t)z * SEQ * EMB;
#pragma unroll
    for (int mi = 0; mi < 2; mi++)
#pragma unroll
        for (int m8 = 0; m8 < 2; m8++) {
            int row = i0 + r0 + mi * 16 + m8 * 8;
#pragma unroll
            for (int ni = 0; ni < 8; ni++) {
                int col = n0 + cb + ni * 8;
                float f0 = (acc[mi][ni][m8 * 2 + 0] + bias[col])     * scale;
                float f1 = (acc[mi][ni][m8 * 2 + 1] + bias[col + 1]) * scale;
                __nv_bfloat162 p = __floats2bfloat162_rn(f0, f1);
                *(uint32_t*)(O + (size_t)row * EMB + col) = *(uint32_t*)&p;
            }
        }
}

// ---------------- E = exp(QK^T/8) (e4m3) + row sums ----------------------------
__global__ __launch_bounds__(256) void qk_kernel(
    const __nv_bfloat16* __restrict__ QKV, float* __restrict__ rsumg)
{
    __shared__ __align__(16) __nv_bfloat16 As[2][128 * PADK];
    __shared__ __align__(16) __nv_bfloat16 Bs[2][128 * PADK];
    __shared__ float rsum[128];
    int j0 = blockIdx.x * 128, i0 = blockIdx.y * 128, h = blockIdx.z;
    if (threadIdx.x < 128) rsum[threadIdx.x] = 0.f;

    float acc[2][8][4];
    gemm_core<128>(QKV + (size_t)i0 * EMB + h * HD, EMB,
                   QKV + (size_t)SEQ * EMB + (size_t)j0 * EMB + h * HD, EMB,
                   HD / 32, As[0], Bs[0], acc);

    int lane = threadIdx.x & 31, wid = threadIdx.x >> 5;
    int wm = wid >> 1, wn = wid & 1;
    int r0 = wm * 32 + (lane >> 2), cb = wn * 64 + (lane & 3) * 2;
#pragma unroll
    for (int mi = 0; mi < 2; mi++)
#pragma unroll
        for (int m8 = 0; m8 < 2; m8++) {
            int lrow = r0 + mi * 16 + m8 * 8;
            int row = i0 + lrow;
            unsigned char* O = g_E8 + ((size_t)h * SEQ + row) * SEQ + j0;
            float rs = 0.f;
#pragma unroll
            for (int ni = 0; ni < 8; ni++) {
                float e0 = __expf(acc[mi][ni][m8 * 2 + 0]);
                float e1 = __expf(acc[mi][ni][m8 * 2 + 1]);
                rs += e0 + e1;
                uint16_t p = pk_e4m3(e0, e1);
                *(uint16_t*)(O + cb + ni * 8) = p;
            }
            rs += __shfl_xor_sync(0xffffffffu, rs, 1);
            rs += __shfl_xor_sync(0xffffffffu, rs, 2);
            if ((lane & 3) == 0) atomicAdd(&rsum[lrow], rs);
        }
    __syncthreads();
    if (threadIdx.x < 128)
        atomicAdd(&rsumg[h * SEQ + i0 + threadIdx.x], rsum[threadIdx.x]);
}

// ---------------- ctx = n * diag(a) * E * (diag(b) V)  (fp8 E, f16 mma) --------
__global__ __launch_bounds__(256) void av_kernel(
    const __half* __restrict__ Vt, const float* __restrict__ avec,
    __nv_bfloat16* __restrict__ ctx)
{
    __shared__ __align__(16) __half As[2][128 * PADK];
    __shared__ __align__(16) __half Bs[2][64 * PADK];
    int i0 = blockIdx.x * 128, h = blockIdx.y;
    const int tid = threadIdx.x, lane = tid & 31, wid = tid >> 5;
    const int wm = wid >> 1, wn = wid & 1;
    const uint32_t asb = smem_u32(As), bsb = smem_u32(Bs);
    const uint32_t ASTG = 128 * PADK * 2, BSTG = 64 * PADK * 2;

    // A loader (fp8 -> f16): thread handles row=tid>>1, 16 bytes at col (tid&1)*16
    const int arow = tid >> 1, acol0 = (tid & 1) * 16;
    const unsigned char* Ag = g_E8 + ((size_t)h * SEQ + i0 + arow) * SEQ + acol0;
    // B loader (f16 direct cp.async): row=tid>>2 (0..63), col (tid&3)*8
    const int br = tid >> 2, bc = (tid & 3) * 8;
    const __half* Bg = Vt + ((size_t)h * HD + br) * SEQ + bc;
    const uint32_t bdst = (uint32_t)(br * PADK + bc) * 2;

    uint32_t aoff[2], boff[2];
#pragma unroll
    for (int mi = 0; mi < 2; mi++) {
        int r = wm * 32 + mi * 16 + (lane & 15);
        int c = (lane >> 4) * 8;
        aoff[mi] = (uint32_t)(r * PADK + c) * 2;
    }
#pragma unroll
    for (int n2 = 0; n2 < 2; n2++) {
        int g = lane >> 3;
        int r = wn * 32 + n2 * 16 + ((g >> 1) << 3) + (lane & 7);
        int c = (g & 1) * 8;
        boff[n2] = (uint32_t)(r * PADK + c) * 2;
    }

    float acc[2][4][4];
#pragma unroll
    for (int mi = 0; mi < 2; mi++)
#pragma unroll
        for (int ni = 0; ni < 4; ni++)
#pragma unroll
            for (int q = 0; q < 4; q++) acc[mi][ni][q] = 0.f;

    uint4 rA = *(const uint4*)Ag;
    cpa16(bsb + bdst, Bg);
    CP_COMMIT();

    for (int c = 0; c < SEQ / 32; c++) {
        int s = c & 1;
        CP_WAIT0();
        __syncthreads();
        // decode fp8 -> f16 SMEM
        {
            const uint32_t* w = (const uint32_t*)&rA;
            __half* dstrow = As[s] + arow * PADK + acol0;
#pragma unroll
            for (int u = 0; u < 4; u++) {
                uint32_t f0, f1;
                asm("cvt.rn.f16x2.e4m3x2 %0, %1;" : "=r"(f0) : "h"((uint16_t)(w[u] & 0xffffu)));
                asm("cvt.rn.f16x2.e4m3x2 %0, %1;" : "=r"(f1) : "h"((uint16_t)(w[u] >> 16)));
                *(uint32_t*)(dstrow + 4 * u)     = f0;
                *(uint32_t*)(dstrow + 4 * u + 2) = f1;
            }
        }
        if (c + 1 < SEQ / 32) {
            rA = *(const uint4*)(Ag + (c + 1) * 32);
            cpa16(bsb + (s ^ 1) * BSTG + bdst, Bg + (c + 1) * 32);
            CP_COMMIT();
        }
        __syncthreads();

        uint32_t ab = asb + s * ASTG, bb = bsb + s * BSTG;
#pragma unroll
        for (int ks = 0; ks < 2; ks++) {
            uint32_t af[2][4];
            ldsm4(af[0][0], af[0][1], af[0][2], af[0][3], ab + aoff[0] + ks * 32);
            ldsm4(af[1][0], af[1][1], af[1][2], af[1][3], ab + aoff[1] + ks * 32);
#pragma unroll
            for (int n2 = 0; n2 < 2; n2++) {
                uint32_t bf[4];
                ldsm4(bf[0], bf[1], bf[2], bf[3], bb + boff[n2] + ks * 32);
                mma16816h(acc[0][2 * n2],     af[0], bf + 0);
                mma16816h(acc[0][2 * n2 + 1], af[0], bf + 2);
                mma16816h(acc[1][2 * n2],     af[1], bf + 0);
                mma16816h(acc[1][2 * n2 + 1], af[1], bf + 2);
            }
        }
        __syncthreads();
    }

    int r0 = wm * 32 + (lane >> 2), cb = wn * 32 + (lane & 3) * 2;
#pragma unroll
    for (int mi = 0; mi < 2; mi++)
#pragma unroll
        for (int m8 = 0; m8 < 2; m8++) {
            int row = i0 + r0 + mi * 16 + m8 * 8;
            float sc = avec[h * SEQ + row] * 2048.0f;
            __nv_bfloat16* O = ctx + (size_t)row * EMB + h * HD;
#pragma unroll
            for (int ni = 0; ni < 4; ni++) {
                float f0 = acc[mi][ni][m8 * 2 + 0] * sc;
                float f1 = acc[mi][ni][m8 * 2 + 1] * sc;
                __nv_bfloat162 p = __floats2bfloat162_rn(f0, f1);
                *(uint32_t*)(O + cb + ni * 8) = *(uint32_t*)&p;
            }
        }
}

// ---------------- y = ctx @ Wo + bo + X ----------------------------------------
__global__ __launch_bounds__(256) void final_kernel(
    const __nv_bfloat16* __restrict__ ctx, const __nv_bfloat16* __restrict__ Wt,
    const float* __restrict__ bo, const float* __restrict__ X,
    float* __restrict__ Y)
{
    __shared__ __align__(16) __nv_bfloat16 As[2][128 * PADK];
    __shared__ __align__(16) __nv_bfloat16 Bs[2][128 * PADK];
    int n0 = blockIdx.x * 128, i0 = blockIdx.y * 128;

    float acc[2][8][4];
    gemm_core<128>(ctx + (size_t)i0 * EMB, EMB,
                   Wt + (size_t)3 * EMB * EMB + (size_t)n0 * EMB, EMB,
                   EMB / 32, As[0], Bs[0], acc);

    int lane = threadIdx.x & 31, wid = threadIdx.x >> 5;
    int wm = wid >> 1, wn = wid & 1;
    int r0 = wm * 32 + (lane >> 2), cb = wn * 64 + (lane & 3) * 2;
#pragma unroll
    for (int mi = 0; mi < 2; mi++)
#pragma unroll
        for (int m8 = 0; m8 < 2; m8++) {
            int row = i0 + r0 + mi * 16 + m8 * 8;
#pragma unroll
            for (int ni = 0; ni < 8; ni++) {
                int col = n0 + cb + ni * 8;
                float2 xv = *(const float2*)(X + (size_t)row * EMB + col);
                float2 o;
                o.x = acc[mi][ni][m8 * 2 + 0] + bo[col]     + xv.x;
                o.y = acc[mi][ni][m8 * 2 + 1] + bo[col + 1] + xv.y;
                *(float2*)(Y + (size_t)row * EMB + col) = o;
            }
        }
}

// ---------------- Sinkhorn vector kernels (fp8 E) ------------------------------
__global__ __launch_bounds__(256) void rowmv_kernel(
    const float* __restrict__ bvec, float* __restrict__ avec)
{
    int h = blockIdx.y;
    __shared__ float bs[SEQ];
    for (int j = threadIdx.x; j < SEQ; j += 256) bs[j] = bvec[h * SEQ + j];
    __syncthreads();
    int w = threadIdx.x >> 5, lane = threadIdx.x & 31;
#pragma unroll
    for (int rr = 0; rr < 2; rr++) {
        int row = blockIdx.x * 16 + w * 2 + rr;
        const uint4* Ep4 = (const uint4*)(g_E8 + ((size_t)h * SEQ + row) * SEQ);
        float sum = 0.f;
#pragma unroll
        for (int k = 0; k < 4; k++) {
            int it = lane + k * 32;
            uint4 u = Ep4[it];
            int base = it * 16;
            const uint32_t wbuf[4] = {u.x, u.y, u.z, u.w};
#pragma unroll
            for (int q = 0; q < 4; q++) {
                float2 lo, hi;
                dec4(wbuf[q], lo, hi);
                sum += lo.x * bs[base + 4 * q] + lo.y * bs[base + 4 * q + 1]
                     + hi.x * bs[base + 4 * q + 2] + hi.y * bs[base + 4 * q + 3];
            }
        }
#pragma unroll
        for (int o = 16; o; o >>= 1) sum += __shfl_xor_sync(0xffffffffu, sum, o);
        if (lane == 0) avec[h * SEQ + row] = MU_F / sum;
    }
}

// col matvec partial: r[j] += sum_i E_ij * a_i over a 128-row chunk
__global__ __launch_bounds__(128) void colmv_kernel(
    const float* __restrict__ avec, float* __restrict__ cvec)
{
    int h = blockIdx.z;
    int j = (blockIdx.x * 128 + threadIdx.x) * 4;
    int i0 = blockIdx.y * 128;
    __shared__ float as_[128];
    if (threadIdx.x < 128) as_[threadIdx.x] = avec[h * SEQ + i0 + threadIdx.x];
    __syncthreads();
    const unsigned char* Ep = g_E8 + (size_t)h * SEQ * SEQ + (size_t)i0 * SEQ + j;
    float s0 = 0.f, s1 = 0.f, s2 = 0.f, s3 = 0.f;
#pragma unroll 4
    for (int i = 0; i < 128; i++) {
        uint32_t w = *(const uint32_t*)(Ep + (size_t)i * SEQ);
        float2 lo, hi;
        dec4(w, lo, hi);
        float a = as_[i];
        s0 += lo.x * a; s1 += lo.y * a; s2 += hi.x * a; s3 += hi.y * a;
    }
    float* c = cvec + h * SEQ + j;
    atomicAdd(c + 0, s0);
    atomicAdd(c + 1, s1);
    atomicAdd(c + 2, s2);
    atomicAdd(c + 3, s3);
}

__global__ void fin_kernel(float* __restrict__ dst, float* __restrict__ r)
{
    int i = blockIdx.x * 256 + threadIdx.x;
    float c = r[i];
    r[i] = 0.f;
    dst[i] = MU_F / c;
}

__global__ void zero_kernel(float* __restrict__ r)
{
    r[blockIdx.x * 256 + threadIdx.x] = 0.f;
}

// ---------------- LayerNorm ---------------------------------------------------
__global__ __launch_bounds__(256) void ln_kernel(
    const float* __restrict__ y, const float* __restrict__ gam,
    const float* __restrict__ bet, float* __restrict__ out)
{
    int row = blockIdx.x;
    const float* yr = y + (size_t)row * EMB;
    int t = threadIdx.x;
    float v0 = yr[t], v1 = yr[t + 256], v2 = yr[t + 512];

    __shared__ float red[8];
    int lane = t & 31, w = t >> 5;

    float s = v0 + v1 + v2;
#pragma unroll
    for (int o = 16; o; o >>= 1) s += __shfl_xor_sync(0xffffffffu, s, o);
    if (lane == 0) red[w] = s;
    __syncthreads();
    float tot = red[0] + red[1] + red[2] + red[3] + red[4] + red[5] + red[6] + red[7];
    float mean = tot * (1.0f / EMB);

    float d0 = v0 - mean, d1 = v1 - mean, d2 = v2 - mean;
    float sq = d0 * d0 + d1 * d1 + d2 * d2;
    __syncthreads();
#pragma unroll
    for (int o = 16; o; o >>= 1) sq += __shfl_xor_sync(0xffffffffu, sq, o);
    if (lane == 0) red[w] = sq;
    __syncthreads();
    float var = (red[0]+red[1]+red[2]+red[3]+red[4]+red[5]+red[6]+red[7]) * (1.0f / EMB);
    float inv = rsqrtf(var + 1e-12f);

    float* outr = out + (size_t)row * EMB;
    outr[t]       = gam[t]       * d0 * inv + bet[t];
    outr[t + 256] = gam[t + 256] * d1 * inv + bet[t + 256];
    outr[t + 512] = gam[t + 512] * d2 * inv + bet[t + 512];
}

// ---------------- launch ------------------------------------------------------
extern "C" void kernel_launch(void* const* d_in, const int* in_sizes, int n_in,
                              void* d_out, int out_size)
{
    const float* X  = (const float*)d_in[0];
    const float* Wq = (const float*)d_in[1];
    const float* bq = (const float*)d_in[2];
    const float* Wk = (const float*)d_in[3];
    const float* bk = (const float*)d_in[4];
    const float* Wv = (const float*)d_in[5];
    const float* bv = (const float*)d_in[6];
    const float* Wo = (const float*)d_in[7];
    const float* bo = (const float*)d_in[8];
    const float* lg = (const float*)d_in[9];
    const float* lb = (const float*)d_in[10];
    float* out = (float*)d_out;

    void *pXb, *pWt, *pQKV, *pVt, *pctx, *pa, *pb, *pr, *py;
    cudaGetSymbolAddress(&pXb, g_Xb);
    cudaGetSymbolAddress(&pWt, g_Wt);
    cudaGetSymbolAddress(&pQKV, g_QKV);
    cudaGetSymbolAddress(&pVt, g_Vt);
    cudaGetSymbolAddress(&pctx, g_ctxb);
    cudaGetSymbolAddress(&pa, g_a);
    cudaGetSymbolAddress(&pb, g_b);
    cudaGetSymbolAddress(&pr, g_r);
    cudaGetSymbolAddress(&py, g_y);

    __nv_bfloat16* Xb  = (__nv_bfloat16*)pXb;
    __nv_bfloat16* Wt  = (__nv_bfloat16*)pWt;
    __nv_bfloat16* QKV = (__nv_bfloat16*)pQKV;
    __half*        Vt  = (__half*)pVt;
    __nv_bfloat16* ctx = (__nv_bfloat16*)pctx;
    float* fa = (float*)pa;
    float* fb = (float*)pb;
    float* fr = (float*)pr;
    float* fy = (float*)py;

    zero_kernel<<<NH * SEQ / 256, 256>>>(fr);

    cvt_kernel<<<SEQ * EMB / 1024, 256>>>(X, Xb);
    wtrans_kernel<<<dim3(EMB / 32, EMB / 32, 4), 256>>>(Wq, Wk, Wv, Wo, Wt);

    proj_kernel<<<dim3(EMB / 128, SEQ / 128, 3), 256>>>(Xb, Wt, bq, bk, bv, QKV);

    qk_kernel<<<dim3(SEQ / 128, SEQ / 128, NH), 256>>>(QKV, fr);

    // Sinkhorn: 3 iterations (first row pass fused into qk row sums)
    fin_kernel<<<NH * SEQ / 256, 256>>>(fa, fr);                       // a1
    colmv_kernel<<<dim3(SEQ / 512, 16, NH), 128>>>(fa, fr);
    fin_kernel<<<NH * SEQ / 256, 256>>>(fb, fr);                       // b1
    rowmv_kernel<<<dim3(SEQ / 16, NH), 256>>>(fb, fa);                 // a2
    colmv_kernel<<<dim3(SEQ / 512, 16, NH), 128>>>(fa, fr);
    fin_kernel<<<NH * SEQ / 256, 256>>>(fb, fr);                       // b2
    rowmv_kernel<<<dim3(SEQ / 16, NH), 256>>>(fb, fa);                 // a3
    colmv_kernel<<<dim3(SEQ / 512, 16, NH), 128>>>(fa, fr);
    fin_kernel<<<NH * SEQ / 256, 256>>>(fb, fr);                       // b3

    vt_prep_kernel<<<dim3(SEQ / 64, NH), 256>>>(QKV + (size_t)2 * SEQ * EMB, fb, Vt);

    av_kernel<<<dim3(SEQ / 128, NH), 256>>>(Vt, fa, ctx);

    final_kernel<<<dim3(EMB / 128, SEQ / 128), 256>>>(ctx, Wt, bo, X, fy);

    ln_kernel<<<SEQ, 256>>>(fy, lg, lb, out);
}

// round 5
// speedup vs baseline: 4.5332x; 1.0706x over previous
#include <cuda_runtime.h>
#include <cuda_bf16.h>
#include <cuda_fp16.h>
#include <cstdint>
#include <cstddef>

#define SEQ 2048
#define EMB 768
#define NH  12
#define HD  64
#define MU_F (1.0f/2048.0f)
#define PADK 40   // padded K-stride (elements) for SMEM tiles

// ---------------- scratch (device globals; no allocation allowed) -------------
__device__ __nv_bfloat16 g_Xb[SEQ*EMB];
__device__ __nv_bfloat16 g_Wt[4*EMB*EMB];           // Wq,Wk,Wv,Wo transposed [n][k]
__device__ __nv_bfloat16 g_QKV[3*SEQ*EMB];          // Q(=q/8), K, V  bf16
__device__ unsigned char g_E8[(size_t)NH*SEQ*SEQ];  // exp(QK^T/8) e4m3 (50.3MB, L2-resident)
__device__ __half g_Vt[NH*HD*SEQ];                  // (diag(b) V)^T per head, f16
__device__ __nv_bfloat16 g_ctxb[SEQ*EMB];
__device__ float g_r[6*NH*SEQ];                     // raw Sinkhorn sums r0..r5
__device__ float g_y[SEQ*EMB];

// ============================ PTX helpers =====================================
__device__ __forceinline__ uint32_t smem_u32(const void* p) {
    uint32_t a;
    asm("{ .reg .u64 t; cvta.to.shared.u64 t, %1; cvt.u32.u64 %0, t; }"
        : "=r"(a) : "l"(p));
    return a;
}
__device__ __forceinline__ void cpa16(uint32_t dst, const void* src) {
    asm volatile("cp.async.cg.shared.global [%0], [%1], 16;" :: "r"(dst), "l"(src));
}
#define CP_COMMIT() asm volatile("cp.async.commit_group;" ::: "memory")
#define CP_WAIT1()  asm volatile("cp.async.wait_group 1;" ::: "memory")
#define CP_WAIT0()  asm volatile("cp.async.wait_group 0;" ::: "memory")

__device__ __forceinline__ void ldsm4(uint32_t& r0, uint32_t& r1, uint32_t& r2,
                                      uint32_t& r3, uint32_t addr) {
    asm volatile("ldmatrix.sync.aligned.m8n8.x4.shared.b16 {%0,%1,%2,%3}, [%4];"
        : "=r"(r0), "=r"(r1), "=r"(r2), "=r"(r3) : "r"(addr));
}
__device__ __forceinline__ void mma16816(float* c, const uint32_t* a, const uint32_t* b) {
    asm volatile("mma.sync.aligned.m16n8k16.row.col.f32.bf16.bf16.f32 "
        "{%0,%1,%2,%3}, {%4,%5,%6,%7}, {%8,%9}, {%0,%1,%2,%3};"
        : "+f"(c[0]), "+f"(c[1]), "+f"(c[2]), "+f"(c[3])
        : "r"(a[0]), "r"(a[1]), "r"(a[2]), "r"(a[3]), "r"(b[0]), "r"(b[1]));
}
__device__ __forceinline__ void mma16816h(float* c, const uint32_t* a, const uint32_t* b) {
    asm volatile("mma.sync.aligned.m16n8k16.row.col.f32.f16.f16.f32 "
        "{%0,%1,%2,%3}, {%4,%5,%6,%7}, {%8,%9}, {%0,%1,%2,%3};"
        : "+f"(c[0]), "+f"(c[1]), "+f"(c[2]), "+f"(c[3])
        : "r"(a[0]), "r"(a[1]), "r"(a[2]), "r"(a[3]), "r"(b[0]), "r"(b[1]));
}

// fp8 e4m3 pack/unpack
__device__ __forceinline__ uint16_t pk_e4m3(float lo, float hi) {
    uint16_t r;
    asm("cvt.rn.satfinite.e4m3x2.f32 %0, %1, %2;" : "=h"(r) : "f"(hi), "f"(lo));
    return r;
}
__device__ __forceinline__ void dec4(uint32_t w, float2& lo, float2& hi) {
    uint32_t f0, f1;
    asm("cvt.rn.f16x2.e4m3x2 %0, %1;" : "=r"(f0) : "h"((uint16_t)(w & 0xffffu)));
    asm("cvt.rn.f16x2.e4m3x2 %0, %1;" : "=r"(f1) : "h"((uint16_t)(w >> 16)));
    lo = __half22float2(*(__half2*)&f0);
    hi = __half22float2(*(__half2*)&f1);
}

// ---------------- mma.sync block-GEMM core, 3-stage pipeline -------------------
// C[128, BN] = A[128, K] * B[BN, K]^T ; A,B bf16 K-major. K in chunks of 32.
// 256 threads = 8 warps (4 M x 2 N); one __syncthreads per chunk.
template<int BN>
__device__ __forceinline__ void gemm_core3(
    const __nv_bfloat16* __restrict__ A, int lda,
    const __nv_bfloat16* __restrict__ B, int ldb,
    int nchunks, __nv_bfloat16* As, __nv_bfloat16* Bs,
    float acc[2][BN/16][4])
{
    constexpr int NF = BN / 16;
    const int tid = threadIdx.x;
    const int lane = tid & 31, wid = tid >> 5;
    const int wm = wid >> 1, wn = wid & 1;
    const uint32_t asb = smem_u32(As), bsb = smem_u32(Bs);
    const uint32_t ASTG = 128 * PADK * 2, BSTG = BN * PADK * 2;

    const int lr = tid >> 2, lc = (tid & 3) * 8;
    const uint32_t adst = (uint32_t)(lr * PADK + lc) * 2;
    const uint32_t bdst = adst;

    uint32_t aoff[2], boff[NF / 2];
#pragma unroll
    for (int mi = 0; mi < 2; mi++) {
        int r = wm * 32 + mi * 16 + (lane & 15);
        int c = (lane >> 4) * 8;
        aoff[mi] = (uint32_t)(r * PADK + c) * 2;
    }
#pragma unroll
    for (int n2 = 0; n2 < NF / 2; n2++) {
        int g = lane >> 3;
        int r = wn * (BN / 2) + n2 * 16 + ((g >> 1) << 3) + (lane & 7);
        int c = (g & 1) * 8;
        boff[n2] = (uint32_t)(r * PADK + c) * 2;
    }

#pragma unroll
    for (int mi = 0; mi < 2; mi++)
#pragma unroll
        for (int ni = 0; ni < NF; ni++)
#pragma unroll
            for (int q = 0; q < 4; q++) acc[mi][ni][q] = 0.f;

    auto issue = [&](int c, int stg) {
        const __nv_bfloat16* Ac = A + c * 32;
        const __nv_bfloat16* Bc = B + c * 32;
        uint32_t ad = asb + (uint32_t)stg * ASTG, bd = bsb + (uint32_t)stg * BSTG;
        cpa16(ad + adst, Ac + (size_t)lr * lda + lc);
        cpa16(ad + adst + 64u * PADK * 2, Ac + (size_t)(lr + 64) * lda + lc);
        cpa16(bd + bdst, Bc + (size_t)lr * ldb + lc);
        if (BN == 128)
            cpa16(bd + bdst + 64u * PADK * 2, Bc + (size_t)(lr + 64) * ldb + lc);
        CP_COMMIT();
    };

    issue(0, 0);
    if (nchunks > 1) issue(1, 1);

    int s = 0, w = 2;
    for (int c = 0; c < nchunks; c++) {
        if (c + 1 < nchunks) { CP_WAIT1(); } else { CP_WAIT0(); }
        __syncthreads();
        if (c + 2 < nchunks) issue(c + 2, w);

        uint32_t ab = asb + (uint32_t)s * ASTG, bb = bsb + (uint32_t)s * BSTG;
#pragma unroll
        for (int ks = 0; ks < 2; ks++) {
            uint32_t af[2][4];
            ldsm4(af[0][0], af[0][1], af[0][2], af[0][3], ab + aoff[0] + ks * 32);
            ldsm4(af[1][0], af[1][1], af[1][2], af[1][3], ab + aoff[1] + ks * 32);
#pragma unroll
            for (int n2 = 0; n2 < NF / 2; n2++) {
                uint32_t bf[4];
                ldsm4(bf[0], bf[1], bf[2], bf[3], bb + boff[n2] + ks * 32);
                mma16816(acc[0][2 * n2],     af[0], bf + 0);
                mma16816(acc[0][2 * n2 + 1], af[0], bf + 2);
                mma16816(acc[1][2 * n2],     af[1], bf + 0);
                mma16816(acc[1][2 * n2 + 1], af[1], bf + 2);
            }
        }
        s = (s == 2) ? 0 : s + 1;
        w = (w == 2) ? 0 : w + 1;
    }
}

#define SMEM_GEMM (6 * 128 * PADK * 2)          // 61440: 3xA + 3xB (BN=128)
#define SMEM_AV   (3 * 128 * PADK * 2 + 3 * 64 * PADK * 2)  // 46080

// ---------------- prep kernels ------------------------------------------------
__global__ __launch_bounds__(256) void cvt_kernel(const float* __restrict__ X,
                                                  __nv_bfloat16* __restrict__ Xb) {
    int i = (blockIdx.x * 256 + threadIdx.x) * 4;
    float4 v = *(const float4*)(X + i);
    __nv_bfloat162 p0 = __floats2bfloat162_rn(v.x, v.y);
    __nv_bfloat162 p1 = __floats2bfloat162_rn(v.z, v.w);
    uint2 o = make_uint2(*(uint32_t*)&p0, *(uint32_t*)&p1);
    *(uint2*)(Xb + i) = o;
}

__global__ __launch_bounds__(256) void wtrans_kernel(
    const float* __restrict__ Wq, const float* __restrict__ Wk,
    const float* __restrict__ Wv, const float* __restrict__ Wo,
    __nv_bfloat16* __restrict__ Wt)
{
    int z = blockIdx.z;
    const float* W = (z == 0) ? Wq : (z == 1) ? Wk : (z == 2) ? Wv : Wo;
    __shared__ float t[32][33];
    int n0 = blockIdx.x * 32, k0 = blockIdx.y * 32;
    int tx = threadIdx.x & 31, ty = threadIdx.x >> 5;
#pragma unroll
    for (int r = 0; r < 4; r++)
        t[ty + r * 8][tx] = W[(size_t)(k0 + ty + r * 8) * EMB + n0 + tx];
    __syncthreads();
    __nv_bfloat16* O = Wt + (size_t)z * EMB * EMB;
#pragma unroll
    for (int r = 0; r < 4; r++)
        O[(size_t)(n0 + ty + r * 8) * EMB + k0 + tx] = __float2bfloat16(t[tx][ty + r * 8]);
}

// Vt[h][d][j] = V[j][h*64+d] * (MU / r5_raw[h][j])   (f16)
__global__ __launch_bounds__(256) void vt_prep_kernel(
    const __nv_bfloat16* __restrict__ Vb, const float* __restrict__ braw,
    __half* __restrict__ Vt)
{
    int h = blockIdx.y, j0 = blockIdx.x * 64;
    __shared__ float t[64][65];
    int tid = threadIdx.x;
    int jj = tid >> 2, d0 = (tid & 3) * 16;
    const __nv_bfloat16* src = Vb + (size_t)(j0 + jj) * EMB + h * HD + d0;
    __nv_bfloat16 tmp[16];
    *(uint4*)tmp = *(const uint4*)src;
    *(uint4*)(tmp + 8) = *(const uint4*)(src + 8);
#pragma unroll
    for (int q = 0; q < 16; q++) t[jj][d0 + q] = __bfloat162float(tmp[q]);
    __syncthreads();
    int dd = tid >> 2, jb = (tid & 3) * 16;
    __half o[16];
#pragma unroll
    for (int q = 0; q < 16; q++) {
        int j = j0 + jb + q;
        float bval = MU_F / braw[h * SEQ + j];
        o[q] = __float2half(t[jb + q][dd] * bval);
    }
    __half* dst = Vt + ((size_t)h * HD + dd) * SEQ + j0 + jb;
    *(uint4*)dst = *(uint4*)o;
    *(uint4*)(dst + 8) = *(uint4*)(o + 8);
}

// ---------------- QKV projection ----------------------------------------------
__global__ __launch_bounds__(256) void proj_kernel(
    const __nv_bfloat16* __restrict__ Xb, const __nv_bfloat16* __restrict__ Wt,
    const float* __restrict__ bq, const float* __restrict__ bk,
    const float* __restrict__ bv, __nv_bfloat16* __restrict__ Out)
{
    extern __shared__ char dsm[];
    __nv_bfloat16* As = (__nv_bfloat16*)dsm;
    __nv_bfloat16* Bs = (__nv_bfloat16*)(dsm + 3 * 128 * PADK * 2);
    int z = blockIdx.z;
    int n0 = blockIdx.x * 128, i0 = blockIdx.y * 128;
    const float* bias = (z == 0) ? bq : (z == 1) ? bk : bv;
    float scale = (z == 0) ? 0.125f : 1.0f;

    float acc[2][8][4];
    gemm_core3<128>(Xb + (size_t)i0 * EMB, EMB,
                    Wt + (size_t)z * EMB * EMB + (size_t)n0 * EMB, EMB,
                    EMB / 32, As, Bs, acc);

    int lane = threadIdx.x & 31, wid = threadIdx.x >> 5;
    int wm = wid >> 1, wn = wid & 1;
    int r0 = wm * 32 + (lane >> 2), cb = wn * 64 + (lane & 3) * 2;
    __nv_bfloat16* O = Out + (size_t)z * SEQ * EMB;
#pragma unroll
    for (int mi = 0; mi < 2; mi++)
#pragma unroll
        for (int m8 = 0; m8 < 2; m8++) {
            int row = i0 + r0 + mi * 16 + m8 * 8;
#pragma unroll
            for (int ni = 0; ni < 8; ni++) {
                int col = n0 + cb + ni * 8;
                float f0 = (acc[mi][ni][m8 * 2 + 0] + bias[col])     * scale;
                float f1 = (acc[mi][ni][m8 * 2 + 1] + bias[col + 1]) * scale;
                __nv_bfloat162 p = __floats2bfloat162_rn(f0, f1);
                *(uint32_t*)(O + (size_t)row * EMB + col) = *(uint32_t*)&p;
            }
        }
}

// ---------------- E = exp(QK^T/8) (e4m3) + raw row sums -> r0 ------------------
__global__ __launch_bounds__(256) void qk_kernel(
    const __nv_bfloat16* __restrict__ QKV, float* __restrict__ rsumg)
{
    extern __shared__ char dsm[];
    __nv_bfloat16* As = (__nv_bfloat16*)dsm;
    __nv_bfloat16* Bs = (__nv_bfloat16*)(dsm + 3 * 128 * PADK * 2);
    int j0 = blockIdx.x * 128, i0 = blockIdx.y * 128, h = blockIdx.z;

    float acc[2][8][4];
    gemm_core3<128>(QKV + (size_t)i0 * EMB + h * HD, EMB,
                    QKV + (size_t)SEQ * EMB + (size_t)j0 * EMB + h * HD, EMB,
                    HD / 32, As, Bs, acc);

    // epilogue: pack e4m3 into SMEM tile (128 x 144B), coalesced global stores
    unsigned char* Et = (unsigned char*)dsm;
    float* rsumS = (float*)(dsm + 128 * 144);
    int tid = threadIdx.x, lane = tid & 31, wid = tid >> 5;
    int wm = wid >> 1, wn = wid & 1;
    int r0 = wm * 32 + (lane >> 2), cb = wn * 64 + (lane & 3) * 2;

    __syncthreads();                 // all mma reads of smem done
    if (tid < 128) rsumS[tid] = 0.f;

    float rs_sv[4];
    int lrow_sv[4];
    int idx = 0;
#pragma unroll
    for (int mi = 0; mi < 2; mi++)
#pragma unroll
        for (int m8 = 0; m8 < 2; m8++) {
            int lrow = r0 + mi * 16 + m8 * 8;
            float rs = 0.f;
#pragma unroll
            for (int ni = 0; ni < 8; ni++) {
                float e0 = __expf(acc[mi][ni][m8 * 2 + 0]);
                float e1 = __expf(acc[mi][ni][m8 * 2 + 1]);
                rs += e0 + e1;
                *(uint16_t*)(Et + lrow * 144 + cb + ni * 8) = pk_e4m3(e0, e1);
            }
            rs += __shfl_xor_sync(0xffffffffu, rs, 1);
            rs += __shfl_xor_sync(0xffffffffu, rs, 2);
            rs_sv[idx] = rs; lrow_sv[idx] = lrow; idx++;
        }
    __syncthreads();
#pragma unroll
    for (int q = 0; q < 4; q++)
        if ((lane & 3) == 0) atomicAdd(&rsumS[lrow_sv[q]], rs_sv[q]);
    __syncthreads();

    int row = tid >> 1, half = (tid & 1) * 64;
    const uint4* src = (const uint4*)(Et + row * 144 + half);
    uint4* dst = (uint4*)(g_E8 + ((size_t)h * SEQ + i0 + row) * SEQ + j0 + half);
    dst[0] = src[0]; dst[1] = src[1]; dst[2] = src[2]; dst[3] = src[3];
    if (tid < 128)
        atomicAdd(&rsumg[h * SEQ + i0 + tid], rsumS[tid]);
}

// ---------------- ctx = diag(1/r4) * E * (diag(b) V)  (fp8 E, f16 mma) ---------
__global__ __launch_bounds__(256) void av_kernel(
    const __half* __restrict__ Vt, const float* __restrict__ araw,
    __nv_bfloat16* __restrict__ ctx)
{
    extern __shared__ char dsm[];
    __half* As = (__half*)dsm;                        // 3 stages 128x40
    __half* Bs = (__half*)(dsm + 3 * 128 * PADK * 2); // 3 stages 64x40
    int i0 = blockIdx.x * 128, h = blockIdx.y;
    const int tid = threadIdx.x, lane = tid & 31, wid = tid >> 5;
    const int wm = wid >> 1, wn = wid & 1;
    const uint32_t asb = smem_u32(As), bsb = smem_u32(Bs);
    const uint32_t ASTG = 128 * PADK * 2, BSTG = 64 * PADK * 2;
    const int NCH = SEQ / 32;

    const int arow = tid >> 1, acol = (tid & 1) * 16;
    const unsigned char* Ag = g_E8 + ((size_t)h * SEQ + i0 + arow) * SEQ + acol;
    const int br = tid >> 2, bc = (tid & 3) * 8;
    const __half* Bg = Vt + ((size_t)h * HD + br) * SEQ + bc;
    const uint32_t bdst = (uint32_t)(br * PADK + bc) * 2;

    uint32_t aoff[2], boff[2];
#pragma unroll
    for (int mi = 0; mi < 2; mi++) {
        int r = wm * 32 + mi * 16 + (lane & 15);
        int c = (lane >> 4) * 8;
        aoff[mi] = (uint32_t)(r * PADK + c) * 2;
    }
#pragma unroll
    for (int n2 = 0; n2 < 2; n2++) {
        int g = lane >> 3;
        int r = wn * 32 + n2 * 16 + ((g >> 1) << 3) + (lane & 7);
        int c = (g & 1) * 8;
        boff[n2] = (uint32_t)(r * PADK + c) * 2;
    }

    float acc[2][4][4];
#pragma unroll
    for (int mi = 0; mi < 2; mi++)
#pragma unroll
        for (int ni = 0; ni < 4; ni++)
#pragma unroll
            for (int q = 0; q < 4; q++) acc[mi][ni][q] = 0.f;

    auto decode = [&](const uint4& r, int stg) {
        const uint32_t* wv = (const uint32_t*)&r;
        __half* d = As + stg * (128 * PADK) + arow * PADK + acol;
#pragma unroll
        for (int u = 0; u < 4; u++) {
            uint32_t f0, f1;
            asm("cvt.rn.f16x2.e4m3x2 %0, %1;" : "=r"(f0) : "h"((uint16_t)(wv[u] & 0xffffu)));
            asm("cvt.rn.f16x2.e4m3x2 %0, %1;" : "=r"(f1) : "h"((uint16_t)(wv[u] >> 16)));
            *(uint32_t*)(d + 4 * u)     = f0;
            *(uint32_t*)(d + 4 * u + 2) = f1;
        }
    };
    auto issueB = [&](int c, int stg) {
        cpa16(bsb + (uint32_t)stg * BSTG + bdst, Bg + c * 32);
        CP_COMMIT();
    };

    uint4 rA = *(const uint4*)Ag;
    decode(rA, 0);
    rA = *(const uint4*)(Ag + 32);
    decode(rA, 1);
    rA = *(const uint4*)(Ag + 64);
    issueB(0, 0);
    issueB(1, 1);

    int s = 0, w = 2;
    for (int c = 0; c < NCH; c++) {
        if (c + 1 < NCH) { CP_WAIT1(); } else { CP_WAIT0(); }
        __syncthreads();
        if (c + 2 < NCH) {
            decode(rA, w);
            if (c + 3 < NCH) rA = *(const uint4*)(Ag + (c + 3) * 32);
            issueB(c + 2, w);
        }
        uint32_t ab = asb + (uint32_t)s * ASTG, bb = bsb + (uint32_t)s * BSTG;
#pragma unroll
        for (int ks = 0; ks < 2; ks++) {
            uint32_t af[2][4];
            ldsm4(af[0][0], af[0][1], af[0][2], af[0][3], ab + aoff[0] + ks * 32);
            ldsm4(af[1][0], af[1][1], af[1][2], af[1][3], ab + aoff[1] + ks * 32);
#pragma unroll
            for (int n2 = 0; n2 < 2; n2++) {
                uint32_t bf[4];
                ldsm4(bf[0], bf[1], bf[2], bf[3], bb + boff[n2] + ks * 32);
                mma16816h(acc[0][2 * n2],     af[0], bf + 0);
                mma16816h(acc[0][2 * n2 + 1], af[0], bf + 2);
                mma16816h(acc[1][2 * n2],     af[1], bf + 0);
                mma16816h(acc[1][2 * n2 + 1], af[1], bf + 2);
            }
        }
        s = (s == 2) ? 0 : s + 1;
        w = (w == 2) ? 0 : w + 1;
    }

    int r0 = wm * 32 + (lane >> 2), cb = wn * 32 + (lane & 3) * 2;
#pragma unroll
    for (int mi = 0; mi < 2; mi++)
#pragma unroll
        for (int m8 = 0; m8 < 2; m8++) {
            int row = i0 + r0 + mi * 16 + m8 * 8;
            float sc = 1.0f / araw[h * SEQ + row];   // = MU/r4 * n
            __nv_bfloat16* O = ctx + (size_t)row * EMB + h * HD;
#pragma unroll
            for (int ni = 0; ni < 4; ni++) {
                float f0 = acc[mi][ni][m8 * 2 + 0] * sc;
                float f1 = acc[mi][ni][m8 * 2 + 1] * sc;
                __nv_bfloat162 p = __floats2bfloat162_rn(f0, f1);
                *(uint32_t*)(O + cb + ni * 8) = *(uint32_t*)&p;
            }
        }
}

// ---------------- y = ctx @ Wo + bo + X ----------------------------------------
__global__ __launch_bounds__(256) void final_kernel(
    const __nv_bfloat16* __restrict__ ctx, const __nv_bfloat16* __restrict__ Wt,
    const float* __restrict__ bo, const float* __restrict__ X,
    float* __restrict__ Y)
{
    extern __shared__ char dsm[];
    __nv_bfloat16* As = (__nv_bfloat16*)dsm;
    __nv_bfloat16* Bs = (__nv_bfloat16*)(dsm + 3 * 128 * PADK * 2);
    int n0 = blockIdx.x * 128, i0 = blockIdx.y * 128;

    float acc[2][8][4];
    gemm_core3<128>(ctx + (size_t)i0 * EMB, EMB,
                    Wt + (size_t)3 * EMB * EMB + (size_t)n0 * EMB, EMB,
                    EMB / 32, As, Bs, acc);

    int lane = threadIdx.x & 31, wid = threadIdx.x >> 5;
    int wm = wid >> 1, wn = wid & 1;
    int r0 = wm * 32 + (lane >> 2), cb = wn * 64 + (lane & 3) * 2;
#pragma unroll
    for (int mi = 0; mi < 2; mi++)
#pragma unroll
        for (int m8 = 0; m8 < 2; m8++) {
            int row = i0 + r0 + mi * 16 + m8 * 8;
#pragma unroll
            for (int ni = 0; ni < 8; ni++) {
                int col = n0 + cb + ni * 8;
                float2 xv = *(const float2*)(X + (size_t)row * EMB + col);
                float2 o;
                o.x = acc[mi][ni][m8 * 2 + 0] + bo[col]     + xv.x;
                o.y = acc[mi][ni][m8 * 2 + 1] + bo[col + 1] + xv.y;
                *(float2*)(Y + (size_t)row * EMB + col) = o;
            }
        }
}

// ---------------- Sinkhorn vector kernels (fp8 E, invert-on-load) --------------
// out_raw[i] = sum_j E_ij * (MU / in_raw[j])
__global__ __launch_bounds__(256) void rowmv_kernel(
    const float* __restrict__ braw, float* __restrict__ outraw)
{
    int h = blockIdx.y;
    __shared__ float bs[SEQ];
    for (int j = threadIdx.x; j < SEQ; j += 256)
        bs[j] = MU_F / braw[h * SEQ + j];
    __syncthreads();
    int w = threadIdx.x >> 5, lane = threadIdx.x & 31;
#pragma unroll
    for (int rr = 0; rr < 2; rr++) {
        int row = blockIdx.x * 16 + w * 2 + rr;
        const uint4* Ep4 = (const uint4*)(g_E8 + ((size_t)h * SEQ + row) * SEQ);
        float sum = 0.f;
#pragma unroll
        for (int k = 0; k < 4; k++) {
            int it = lane + k * 32;
            uint4 u = Ep4[it];
            int base = it * 16;
            const uint32_t wbuf[4] = {u.x, u.y, u.z, u.w};
#pragma unroll
            for (int q = 0; q < 4; q++) {
                float2 lo, hi;
                dec4(wbuf[q], lo, hi);
                sum += lo.x * bs[base + 4 * q] + lo.y * bs[base + 4 * q + 1]
                     + hi.x * bs[base + 4 * q + 2] + hi.y * bs[base + 4 * q + 3];
            }
        }
#pragma unroll
        for (int o = 16; o; o >>= 1) sum += __shfl_xor_sync(0xffffffffu, sum, o);
        if (lane == 0) outraw[h * SEQ + row] = sum;
    }
}

// out_raw[j] += sum_i E_ij * (MU / in_raw[i]) over a 128-row chunk
__global__ __launch_bounds__(128) void colmv_kernel(
    const float* __restrict__ araw, float* __restrict__ outraw)
{
    int h = blockIdx.z;
    int j = (blockIdx.x * 128 + threadIdx.x) * 4;
    int i0 = blockIdx.y * 128;
    __shared__ float as_[128];
    if (threadIdx.x < 128) as_[threadIdx.x] = MU_F / araw[h * SEQ + i0 + threadIdx.x];
    __syncthreads();
    const unsigned char* Ep = g_E8 + (size_t)h * SEQ * SEQ + (size_t)i0 * SEQ + j;
    float s0 = 0.f, s1 = 0.f, s2 = 0.f, s3 = 0.f;
#pragma unroll 4
    for (int i = 0; i < 128; i++) {
        uint32_t w = *(const uint32_t*)(Ep + (size_t)i * SEQ);
        float2 lo, hi;
        dec4(w, lo, hi);
        float a = as_[i];
        s0 += lo.x * a; s1 += lo.y * a; s2 += hi.x * a; s3 += hi.y * a;
    }
    float* c = outraw + h * SEQ + j;
    atomicAdd(c + 0, s0);
    atomicAdd(c + 1, s1);
    atomicAdd(c + 2, s2);
    atomicAdd(c + 3, s3);
}

__global__ void zero_kernel(float* __restrict__ r)
{
    r[blockIdx.x * 256 + threadIdx.x] = 0.f;
}

// ---------------- LayerNorm ---------------------------------------------------
__global__ __launch_bounds__(256) void ln_kernel(
    const float* __restrict__ y, const float* __restrict__ gam,
    const float* __restrict__ bet, float* __restrict__ out)
{
    int row = blockIdx.x;
    const float* yr = y + (size_t)row * EMB;
    int t = threadIdx.x;
    float v0 = yr[t], v1 = yr[t + 256], v2 = yr[t + 512];

    __shared__ float red[8];
    int lane = t & 31, w = t >> 5;

    float s = v0 + v1 + v2;
#pragma unroll
    for (int o = 16; o; o >>= 1) s += __shfl_xor_sync(0xffffffffu, s, o);
    if (lane == 0) red[w] = s;
    __syncthreads();
    float tot = red[0] + red[1] + red[2] + red[3] + red[4] + red[5] + red[6] + red[7];
    float mean = tot * (1.0f / EMB);

    float d0 = v0 - mean, d1 = v1 - mean, d2 = v2 - mean;
    float sq = d0 * d0 + d1 * d1 + d2 * d2;
    __syncthreads();
#pragma unroll
    for (int o = 16; o; o >>= 1) sq += __shfl_xor_sync(0xffffffffu, sq, o);
    if (lane == 0) red[w] = sq;
    __syncthreads();
    float var = (red[0]+red[1]+red[2]+red[3]+red[4]+red[5]+red[6]+red[7]) * (1.0f / EMB);
    float inv = rsqrtf(var + 1e-12f);

    float* outr = out + (size_t)row * EMB;
    outr[t]       = gam[t]       * d0 * inv + bet[t];
    outr[t + 256] = gam[t + 256] * d1 * inv + bet[t + 256];
    outr[t + 512] = gam[t + 512] * d2 * inv + bet[t + 512];
}

// ---------------- launch ------------------------------------------------------
extern "C" void kernel_launch(void* const* d_in, const int* in_sizes, int n_in,
                              void* d_out, int out_size)
{
    const float* X  = (const float*)d_in[0];
    const float* Wq = (const float*)d_in[1];
    const float* bq = (const float*)d_in[2];
    const float* Wk = (const float*)d_in[3];
    const float* bk = (const float*)d_in[4];
    const float* Wv = (const float*)d_in[5];
    const float* bv = (const float*)d_in[6];
    const float* Wo = (const float*)d_in[7];
    const float* bo = (const float*)d_in[8];
    const float* lg = (const float*)d_in[9];
    const float* lb = (const float*)d_in[10];
    float* out = (float*)d_out;

    void *pXb, *pWt, *pQKV, *pVt, *pctx, *pr, *py;
    cudaGetSymbolAddress(&pXb, g_Xb);
    cudaGetSymbolAddress(&pWt, g_Wt);
    cudaGetSymbolAddress(&pQKV, g_QKV);
    cudaGetSymbolAddress(&pVt, g_Vt);
    cudaGetSymbolAddress(&pctx, g_ctxb);
    cudaGetSymbolAddress(&pr, g_r);
    cudaGetSymbolAddress(&py, g_y);

    __nv_bfloat16* Xb  = (__nv_bfloat16*)pXb;
    __nv_bfloat16* Wt  = (__nv_bfloat16*)pWt;
    __nv_bfloat16* QKV = (__nv_bfloat16*)pQKV;
    __half*        Vt  = (__half*)pVt;
    __nv_bfloat16* ctx = (__nv_bfloat16*)pctx;
    float* fr = (float*)pr;
    float* fy = (float*)py;

    float* r0 = fr + 0 * NH * SEQ;
    float* r1 = fr + 1 * NH * SEQ;
    float* r2 = fr + 2 * NH * SEQ;
    float* r3 = fr + 3 * NH * SEQ;
    float* r4 = fr + 4 * NH * SEQ;
    float* r5 = fr + 5 * NH * SEQ;

    cudaFuncSetAttribute(proj_kernel,  cudaFuncAttributeMaxDynamicSharedMemorySize, SMEM_GEMM);
    cudaFuncSetAttribute(qk_kernel,    cudaFuncAttributeMaxDynamicSharedMemorySize, SMEM_GEMM);
    cudaFuncSetAttribute(av_kernel,    cudaFuncAttributeMaxDynamicSharedMemorySize, SMEM_AV);
    cudaFuncSetAttribute(final_kernel, cudaFuncAttributeMaxDynamicSharedMemorySize, SMEM_GEMM);

    zero_kernel<<<6 * NH * SEQ / 256, 256>>>(fr);

    cvt_kernel<<<SEQ * EMB / 1024, 256>>>(X, Xb);
    wtrans_kernel<<<dim3(EMB / 32, EMB / 32, 4), 256>>>(Wq, Wk, Wv, Wo, Wt);

    proj_kernel<<<dim3(EMB / 128, SEQ / 128, 3), 256, SMEM_GEMM>>>(Xb, Wt, bq, bk, bv, QKV);

    qk_kernel<<<dim3(SEQ / 128, SEQ / 128, NH), 256, SMEM_GEMM>>>(QKV, r0);

    // Sinkhorn: 3 iterations, raw sums, inversion folded into consumers
    colmv_kernel<<<dim3(SEQ / 512, 16, NH), 128>>>(r0, r1);
    rowmv_kernel<<<dim3(SEQ / 16, NH), 256>>>(r1, r2);
    colmv_kernel<<<dim3(SEQ / 512, 16, NH), 128>>>(r2, r3);
    rowmv_kernel<<<dim3(SEQ / 16, NH), 256>>>(r3, r4);
    colmv_kernel<<<dim3(SEQ / 512, 16, NH), 128>>>(r4, r5);

    vt_prep_kernel<<<dim3(SEQ / 64, NH), 256>>>(QKV + (size_t)2 * SEQ * EMB, r5, Vt);

    av_kernel<<<dim3(SEQ / 128, NH), 256, SMEM_AV>>>(Vt, r4, ctx);

    final_kernel<<<dim3(EMB / 128, SEQ / 128), 256, SMEM_GEMM>>>(ctx, Wt, bo, X, fy);

    ln_kernel<<<SEQ, 256>>>(fy, lg, lb, out);
}

// round 8
// speedup vs baseline: 4.9923x; 1.1013x over previous
#include <cuda_runtime.h>
#include <cuda_bf16.h>
#include <cuda_fp16.h>
#include <cstdint>
#include <cstddef>

#define SEQ 2048
#define EMB 768
#define NH  12
#define HD  64
#define MU_F (1.0f/2048.0f)
#define PADK 40     // bf16 GEMM smem row stride (elements)
#define APAD 48     // fp8 av smem row stride (bytes)
#define VSCALE 16.0f

// ---------------- scratch (device globals; no allocation allowed) -------------
__device__ __nv_bfloat16 g_Xb[SEQ*EMB];
__device__ __nv_bfloat16 g_Wt[4*EMB*EMB];           // Wq,Wk,Wv,Wo transposed [n][k]
__device__ __nv_bfloat16 g_QKV[3*SEQ*EMB];          // Q(=q/8), K, V  bf16
__device__ unsigned char g_E8[(size_t)NH*SEQ*SEQ];  // exp(QK^T/8) e4m3 (50.3MB)
__device__ unsigned char g_Vt8[NH*HD*SEQ];          // (diag(b) V)^T * 16, e4m3
__device__ __nv_bfloat16 g_ctxb[SEQ*EMB];
__device__ float g_r[6*NH*SEQ];                     // raw Sinkhorn sums r0..r5
__device__ float g_y[SEQ*EMB];

// ============================ PTX helpers =====================================
__device__ __forceinline__ uint32_t smem_u32(const void* p) {
    uint32_t a;
    asm("{ .reg .u64 t; cvta.to.shared.u64 t, %1; cvt.u32.u64 %0, t; }"
        : "=r"(a) : "l"(p));
    return a;
}
__device__ __forceinline__ void cpa16(uint32_t dst, const void* src) {
    asm volatile("cp.async.cg.shared.global [%0], [%1], 16;" :: "r"(dst), "l"(src));
}
#define CP_COMMIT() asm volatile("cp.async.commit_group;" ::: "memory")
#define CP_WAIT1()  asm volatile("cp.async.wait_group 1;" ::: "memory")
#define CP_WAIT0()  asm volatile("cp.async.wait_group 0;" ::: "memory")

__device__ __forceinline__ void ldsm4(uint32_t& r0, uint32_t& r1, uint32_t& r2,
                                      uint32_t& r3, uint32_t addr) {
    asm volatile("ldmatrix.sync.aligned.m8n8.x4.shared.b16 {%0,%1,%2,%3}, [%4];"
        : "=r"(r0), "=r"(r1), "=r"(r2), "=r"(r3) : "r"(addr));
}
__device__ __forceinline__ void mma16816(float* c, const uint32_t* a, const uint32_t* b) {
    asm volatile("mma.sync.aligned.m16n8k16.row.col.f32.bf16.bf16.f32 "
        "{%0,%1,%2,%3}, {%4,%5,%6,%7}, {%8,%9}, {%0,%1,%2,%3};"
        : "+f"(c[0]), "+f"(c[1]), "+f"(c[2]), "+f"(c[3])
        : "r"(a[0]), "r"(a[1]), "r"(a[2]), "r"(a[3]), "r"(b[0]), "r"(b[1]));
}
__device__ __forceinline__ void mma16832q(float* c, const uint32_t* a, const uint32_t* b) {
    asm volatile("mma.sync.aligned.m16n8k32.row.col.f32.e4m3.e4m3.f32 "
        "{%0,%1,%2,%3}, {%4,%5,%6,%7}, {%8,%9}, {%0,%1,%2,%3};"
        : "+f"(c[0]), "+f"(c[1]), "+f"(c[2]), "+f"(c[3])
        : "r"(a[0]), "r"(a[1]), "r"(a[2]), "r"(a[3]), "r"(b[0]), "r"(b[1]));
}

// fp8 e4m3 pack/unpack
__device__ __forceinline__ uint16_t pk_e4m3(float lo, float hi) {
    uint16_t r;
    asm("cvt.rn.satfinite.e4m3x2.f32 %0, %1, %2;" : "=h"(r) : "f"(hi), "f"(lo));
    return r;
}
__device__ __forceinline__ void dec4(uint32_t w, float2& lo, float2& hi) {
    uint32_t f0, f1;
    asm("cvt.rn.f16x2.e4m3x2 %0, %1;" : "=r"(f0) : "h"((uint16_t)(w & 0xffffu)));
    asm("cvt.rn.f16x2.e4m3x2 %0, %1;" : "=r"(f1) : "h"((uint16_t)(w >> 16)));
    lo = __half22float2(*(__half2*)&f0);
    hi = __half22float2(*(__half2*)&f1);
}

// ---------------- mma.sync block-GEMM core, 3-stage pipeline (bf16) ------------
template<int BN>
__device__ __forceinline__ void gemm_core3(
    const __nv_bfloat16* __restrict__ A, int lda,
    const __nv_bfloat16* __restrict__ B, int ldb,
    int nchunks, __nv_bfloat16* As, __nv_bfloat16* Bs,
    float acc[2][BN/16][4])
{
    constexpr int NF = BN / 16;
    const int tid = threadIdx.x;
    const int lane = tid & 31, wid = tid >> 5;
    const int wm = wid >> 1, wn = wid & 1;
    const uint32_t asb = smem_u32(As), bsb = smem_u32(Bs);
    const uint32_t ASTG = 128 * PADK * 2, BSTG = BN * PADK * 2;

    const int lr = tid >> 2, lc = (tid & 3) * 8;
    const uint32_t adst = (uint32_t)(lr * PADK + lc) * 2;
    const uint32_t bdst = adst;

    uint32_t aoff[2], boff[NF / 2];
#pragma unroll
    for (int mi = 0; mi < 2; mi++) {
        int r = wm * 32 + mi * 16 + (lane & 15);
        int c = (lane >> 4) * 8;
        aoff[mi] = (uint32_t)(r * PADK + c) * 2;
    }
#pragma unroll
    for (int n2 = 0; n2 < NF / 2; n2++) {
        int g = lane >> 3;
        int r = wn * (BN / 2) + n2 * 16 + ((g >> 1) << 3) + (lane & 7);
        int c = (g & 1) * 8;
        boff[n2] = (uint32_t)(r * PADK + c) * 2;
    }

#pragma unroll
    for (int mi = 0; mi < 2; mi++)
#pragma unroll
        for (int ni = 0; ni < NF; ni++)
#pragma unroll
            for (int q = 0; q < 4; q++) acc[mi][ni][q] = 0.f;

    auto issue = [&](int c, int stg) {
        const __nv_bfloat16* Ac = A + c * 32;
        const __nv_bfloat16* Bc = B + c * 32;
        uint32_t ad = asb + (uint32_t)stg * ASTG, bd = bsb + (uint32_t)stg * BSTG;
        cpa16(ad + adst, Ac + (size_t)lr * lda + lc);
        cpa16(ad + adst + 64u * PADK * 2, Ac + (size_t)(lr + 64) * lda + lc);
        cpa16(bd + bdst, Bc + (size_t)lr * ldb + lc);
        if (BN == 128)
            cpa16(bd + bdst + 64u * PADK * 2, Bc + (size_t)(lr + 64) * ldb + lc);
        CP_COMMIT();
    };

    issue(0, 0);
    if (nchunks > 1) issue(1, 1);

    int s = 0, w = 2;
    for (int c = 0; c < nchunks; c++) {
        if (c + 1 < nchunks) { CP_WAIT1(); } else { CP_WAIT0(); }
        __syncthreads();
        if (c + 2 < nchunks) issue(c + 2, w);

        uint32_t ab = asb + (uint32_t)s * ASTG, bb = bsb + (uint32_t)s * BSTG;
#pragma unroll
        for (int ks = 0; ks < 2; ks++) {
            uint32_t af[2][4];
            ldsm4(af[0][0], af[0][1], af[0][2], af[0][3], ab + aoff[0] + ks * 32);
            ldsm4(af[1][0], af[1][1], af[1][2], af[1][3], ab + aoff[1] + ks * 32);
#pragma unroll
            for (int n2 = 0; n2 < NF / 2; n2++) {
                uint32_t bf[4];
                ldsm4(bf[0], bf[1], bf[2], bf[3], bb + boff[n2] + ks * 32);
                mma16816(acc[0][2 * n2],     af[0], bf + 0);
                mma16816(acc[0][2 * n2 + 1], af[0], bf + 2);
                mma16816(acc[1][2 * n2],     af[1], bf + 0);
                mma16816(acc[1][2 * n2 + 1], af[1], bf + 2);
            }
        }
        s = (s == 2) ? 0 : s + 1;
        w = (w == 2) ? 0 : w + 1;
    }
}

#define SMEM_GEMM (6 * 128 * PADK * 2)                      // 61440
#define SMEM_AV   (3 * 128 * APAD + 3 * 64 * APAD)          // 27648

// ---------------- fused prep: zero r, cvt X->bf16, transpose W -----------------
__global__ __launch_bounds__(256) void prep_kernel(
    const float* __restrict__ X,
    const float* __restrict__ Wq, const float* __restrict__ Wk,
    const float* __restrict__ Wv, const float* __restrict__ Wo,
    __nv_bfloat16* __restrict__ Xb, __nv_bfloat16* __restrict__ Wt,
    float* __restrict__ r)
{
    __shared__ float t[32][33];
    int b = blockIdx.x;
    if (b < 576) {                       // zero 6*NH*SEQ floats
        r[b * 256 + threadIdx.x] = 0.f;
        return;
    }
    b -= 576;
    if (b < 1536) {                      // cvt X
        int i = (b * 256 + threadIdx.x) * 4;
        float4 v = *(const float4*)(X + i);
        __nv_bfloat162 p0 = __floats2bfloat162_rn(v.x, v.y);
        __nv_bfloat162 p1 = __floats2bfloat162_rn(v.z, v.w);
        uint2 o = make_uint2(*(uint32_t*)&p0, *(uint32_t*)&p1);
        *(uint2*)(Xb + i) = o;
        return;
    }
    b -= 1536;                           // wtrans: 4 * 24 * 24 blocks
    int z = b / 576;
    int rem = b % 576;
    int n0 = (rem % 24) * 32, k0 = (rem / 24) * 32;
    const float* W = (z == 0) ? Wq : (z == 1) ? Wk : (z == 2) ? Wv : Wo;
    int tx = threadIdx.x & 31, ty = threadIdx.x >> 5;
#pragma unroll
    for (int q = 0; q < 4; q++)
        t[ty + q * 8][tx] = W[(size_t)(k0 + ty + q * 8) * EMB + n0 + tx];
    __syncthreads();
    __nv_bfloat16* O = Wt + (size_t)z * EMB * EMB;
#pragma unroll
    for (int q = 0; q < 4; q++)
        O[(size_t)(n0 + ty + q * 8) * EMB + k0 + tx] = __float2bfloat16(t[tx][ty + q * 8]);
}

// Vt8[h][d][j] = e4m3( V[j][h*64+d] * (MU / r5_raw[h][j]) * 16 )
__global__ __launch_bounds__(256) void vt_prep_kernel(
    const __nv_bfloat16* __restrict__ Vb, const float* __restrict__ braw,
    unsigned char* __restrict__ Vt)
{
    int h = blockIdx.y, j0 = blockIdx.x * 64;
    __shared__ float t[64][65];
    int tid = threadIdx.x;
    int jj = tid >> 2, d0 = (tid & 3) * 16;
    const __nv_bfloat16* src = Vb + (size_t)(j0 + jj) * EMB + h * HD + d0;
    __nv_bfloat16 tmp[16];
    *(uint4*)tmp = *(const uint4*)src;
    *(uint4*)(tmp + 8) = *(const uint4*)(src + 8);
#pragma unroll
    for (int q = 0; q < 16; q++) t[jj][d0 + q] = __bfloat162float(tmp[q]);
    __syncthreads();
    int dd = tid >> 2, jb = (tid & 3) * 16;
    uint16_t o[8];
#pragma unroll
    for (int q = 0; q < 8; q++) {
        int j = j0 + jb + 2 * q;
        float b0 = VSCALE * MU_F / braw[h * SEQ + j];
        float b1 = VSCALE * MU_F / braw[h * SEQ + j + 1];
        o[q] = pk_e4m3(t[jb + 2 * q][dd] * b0, t[jb + 2 * q + 1][dd] * b1);
    }
    unsigned char* dst = Vt + ((size_t)h * HD + dd) * SEQ + j0 + jb;
    *(uint4*)dst = *(uint4*)o;
}

// ---------------- QKV projection ----------------------------------------------
__global__ __launch_bounds__(256, 2) void proj_kernel(
    const __nv_bfloat16* __restrict__ Xb, const __nv_bfloat16* __restrict__ Wt,
    const float* __restrict__ bq, const float* __restrict__ bk,
    const float* __restrict__ bv, __nv_bfloat16* __restrict__ Out)
{
    extern __shared__ char dsm[];
    __nv_bfloat16* As = (__nv_bfloat16*)dsm;
    __nv_bfloat16* Bs = (__nv_bfloat16*)(dsm + 3 * 128 * PADK * 2);
    int z = blockIdx.z;
    int n0 = blockIdx.x * 128, i0 = blockIdx.y * 128;
    const float* bias = (z == 0) ? bq : (z == 1) ? bk : bv;
    float scale = (z == 0) ? 0.125f : 1.0f;

    float acc[2][8][4];
    gemm_core3<128>(Xb + (size_t)i0 * EMB, EMB,
                    Wt + (size_t)z * EMB * EMB + (size_t)n0 * EMB, EMB,
                    EMB / 32, As, Bs, acc);

    int lane = threadIdx.x & 31, wid = threadIdx.x >> 5;
    int wm = wid >> 1, wn = wid & 1;
    int r0 = wm * 32 + (lane >> 2), cb = wn * 64 + (lane & 3) * 2;
    __nv_bfloat16* O = Out + (size_t)z * SEQ * EMB;
#pragma unroll
    for (int mi = 0; mi < 2; mi++)
#pragma unroll
        for (int m8 = 0; m8 < 2; m8++) {
            int row = i0 + r0 + mi * 16 + m8 * 8;
#pragma unroll
            for (int ni = 0; ni < 8; ni++) {
                int col = n0 + cb + ni * 8;
                float f0 = (acc[mi][ni][m8 * 2 + 0] + bias[col])     * scale;
                float f1 = (acc[mi][ni][m8 * 2 + 1] + bias[col + 1]) * scale;
                __nv_bfloat162 p = __floats2bfloat162_rn(f0, f1);
                *(uint32_t*)(O + (size_t)row * EMB + col) = *(uint32_t*)&p;
            }
        }
}

// ---------------- E = exp(QK^T/8) (e4m3) + raw row sums -> r0 ------------------
__global__ __launch_bounds__(256, 2) void qk_kernel(
    const __nv_bfloat16* __restrict__ QKV, float* __restrict__ rsumg)
{
    extern __shared__ char dsm[];
    __nv_bfloat16* As = (__nv_bfloat16*)dsm;
    __nv_bfloat16* Bs = (__nv_bfloat16*)(dsm + 3 * 128 * PADK * 2);
    int j0 = blockIdx.x * 128, i0 = blockIdx.y * 128, h = blockIdx.z;

    float acc[2][8][4];
    gemm_core3<128>(QKV + (size_t)i0 * EMB + h * HD, EMB,
                    QKV + (size_t)SEQ * EMB + (size_t)j0 * EMB + h * HD, EMB,
                    HD / 32, As, Bs, acc);

    unsigned char* Et = (unsigned char*)dsm;
    float* rsumS = (float*)(dsm + 128 * 144);
    int tid = threadIdx.x, lane = tid & 31, wid = tid >> 5;
    int wm = wid >> 1, wn = wid & 1;
    int r0 = wm * 32 + (lane >> 2), cb = wn * 64 + (lane & 3) * 2;

    __syncthreads();
    if (tid < 128) rsumS[tid] = 0.f;

    float rs_sv[4];
    int lrow_sv[4];
    int idx = 0;
#pragma unroll
    for (int mi = 0; mi < 2; mi++)
#pragma unroll
        for (int m8 = 0; m8 < 2; m8++) {
            int lrow = r0 + mi * 16 + m8 * 8;
            float rs = 0.f;
#pragma unroll
            for (int ni = 0; ni < 8; ni++) {
                float e0 = __expf(acc[mi][ni][m8 * 2 + 0]);
                float e1 = __expf(acc[mi][ni][m8 * 2 + 1]);
                rs += e0 + e1;
                *(uint16_t*)(Et + lrow * 144 + cb + ni * 8) = pk_e4m3(e0, e1);
            }
            rs += __shfl_xor_sync(0xffffffffu, rs, 1);
            rs += __shfl_xor_sync(0xffffffffu, rs, 2);
            rs_sv[idx] = rs; lrow_sv[idx] = lrow; idx++;
        }
    __syncthreads();
#pragma unroll
    for (int q = 0; q < 4; q++)
        if ((lane & 3) == 0) atomicAdd(&rsumS[lrow_sv[q]], rs_sv[q]);
    __syncthreads();

    int row = tid >> 1, half = (tid & 1) * 64;
    const uint4* src = (const uint4*)(Et + row * 144 + half);
    uint4* dst = (uint4*)(g_E8 + ((size_t)h * SEQ + i0 + row) * SEQ + j0 + half);
    dst[0] = src[0]; dst[1] = src[1]; dst[2] = src[2]; dst[3] = src[3];
    if (tid < 128)
        atomicAdd(&rsumg[h * SEQ + i0 + tid], rsumS[tid]);
}

// ---------------- ctx = diag(1/r4) * E * (diag(b) V)  — native fp8 mma ---------
__global__ __launch_bounds__(256, 2) void av_kernel(
    const unsigned char* __restrict__ Vt, const float* __restrict__ araw,
    __nv_bfloat16* __restrict__ ctx)
{
    extern __shared__ char dsm[];
    char* As = dsm;                      // 3 stages 128 x APAD
    char* Bs = dsm + 3 * 128 * APAD;     // 3 stages 64 x APAD
    int i0 = blockIdx.x * 128, h = blockIdx.y;
    const int tid = threadIdx.x, lane = tid & 31, wid = tid >> 5;
    const int wm = wid >> 1, wn = wid & 1;
    const uint32_t asb = smem_u32(As), bsb = smem_u32(Bs);
    const uint32_t ASTG = 128 * APAD, BSTG = 64 * APAD;
    const int NCH = SEQ / 32;

    // A loader: 256 threads, 16B each: row=tid>>1 (0..127), col=(tid&1)*16
    const int arow = tid >> 1, acol = (tid & 1) * 16;
    const unsigned char* Ag = g_E8 + ((size_t)h * SEQ + i0 + arow) * SEQ + acol;
    const uint32_t adst = (uint32_t)(arow * APAD + acol);
    // B loader: first 128 threads, 16B each: row=tid>>1 (0..63), col=(tid&1)*16
    const int brow = tid >> 1, bcol = (tid & 1) * 16;
    const unsigned char* Bg = Vt + ((size_t)h * HD + brow) * SEQ + bcol;
    const uint32_t bdst = (uint32_t)(brow * APAD + bcol);
    const bool bload = (tid < 128);

    uint32_t aoff[2], boff[2];
#pragma unroll
    for (int mi = 0; mi < 2; mi++) {
        int r = wm * 32 + mi * 16 + (lane & 15);
        aoff[mi] = (uint32_t)(r * APAD + (lane >> 4) * 16);
    }
#pragma unroll
    for (int n2 = 0; n2 < 2; n2++) {
        int g = lane >> 3;
        int r = wn * 32 + n2 * 16 + ((g >> 1) << 3) + (lane & 7);
        boff[n2] = (uint32_t)(r * APAD + (g & 1) * 16);
    }

    float acc[2][4][4];
#pragma unroll
    for (int mi = 0; mi < 2; mi++)
#pragma unroll
        for (int ni = 0; ni < 4; ni++)
#pragma unroll
            for (int q = 0; q < 4; q++) acc[mi][ni][q] = 0.f;

    auto issue = [&](int c, int stg) {
        cpa16(asb + (uint32_t)stg * ASTG + adst, Ag + c * 32);
        if (bload) cpa16(bsb + (uint32_t)stg * BSTG + bdst, Bg + c * 32);
        CP_COMMIT();
    };

    issue(0, 0);
    issue(1, 1);

    int s = 0, w = 2;
    for (int c = 0; c < NCH; c++) {
        if (c + 1 < NCH) { CP_WAIT1(); } else { CP_WAIT0(); }
        __syncthreads();
        if (c + 2 < NCH) issue(c + 2, w);

        uint32_t ab = asb + (uint32_t)s * ASTG, bb = bsb + (uint32_t)s * BSTG;
        uint32_t af[2][4];
        ldsm4(af[0][0], af[0][1], af[0][2], af[0][3], ab + aoff[0]);
        ldsm4(af[1][0], af[1][1], af[1][2], af[1][3], ab + aoff[1]);
#pragma unroll
        for (int n2 = 0; n2 < 2; n2++) {
            uint32_t bf[4];
            ldsm4(bf[0], bf[1], bf[2], bf[3], bb + boff[n2]);
            mma16832q(acc[0][2 * n2],     af[0], bf + 0);
            mma16832q(acc[0][2 * n2 + 1], af[0], bf + 2);
            mma16832q(acc[1][2 * n2],     af[1], bf + 0);
            mma16832q(acc[1][2 * n2 + 1], af[1], bf + 2);
        }
        s = (s == 2) ? 0 : s + 1;
        w = (w == 2) ? 0 : w + 1;
    }

    int r0 = wm * 32 + (lane >> 2), cb = wn * 32 + (lane & 3) * 2;
#pragma unroll
    for (int mi = 0; mi < 2; mi++)
#pragma unroll
        for (int m8 = 0; m8 < 2; m8++) {
            int row = i0 + r0 + mi * 16 + m8 * 8;
            float sc = 1.0f / (araw[h * SEQ + row] * VSCALE);
            __nv_bfloat16* O = ctx + (size_t)row * EMB + h * HD;
#pragma unroll
            for (int ni = 0; ni < 4; ni++) {
                float f0 = acc[mi][ni][m8 * 2 + 0] * sc;
                float f1 = acc[mi][ni][m8 * 2 + 1] * sc;
                __nv_bfloat162 p = __floats2bfloat162_rn(f0, f1);
                *(uint32_t*)(O + cb + ni * 8) = *(uint32_t*)&p;
            }
        }
}

// ---------------- y = ctx @ Wo + bo + X ----------------------------------------
__global__ __launch_bounds__(256, 2) void final_kernel(
    const __nv_bfloat16* __restrict__ ctx, const __nv_bfloat16* __restrict__ Wt,
    const float* __restrict__ bo, const float* __restrict__ X,
    float* __restrict__ Y)
{
    extern __shared__ char dsm[];
    __nv_bfloat16* As = (__nv_bfloat16*)dsm;
    __nv_bfloat16* Bs = (__nv_bfloat16*)(dsm + 3 * 128 * PADK * 2);
    int n0 = blockIdx.x * 128, i0 = blockIdx.y * 128;

    float acc[2][8][4];
    gemm_core3<128>(ctx + (size_t)i0 * EMB, EMB,
                    Wt + (size_t)3 * EMB * EMB + (size_t)n0 * EMB, EMB,
                    EMB / 32, As, Bs, acc);

    int lane = threadIdx.x & 31, wid = threadIdx.x >> 5;
    int wm = wid >> 1, wn = wid & 1;
    int r0 = wm * 32 + (lane >> 2), cb = wn * 64 + (lane & 3) * 2;
#pragma unroll
    for (int mi = 0; mi < 2; mi++)
#pragma unroll
        for (int m8 = 0; m8 < 2; m8++) {
            int row = i0 + r0 + mi * 16 + m8 * 8;
#pragma unroll
            for (int ni = 0; ni < 8; ni++) {
                int col = n0 + cb + ni * 8;
                float2 xv = *(const float2*)(X + (size_t)row * EMB + col);
                float2 o;
                o.x = acc[mi][ni][m8 * 2 + 0] + bo[col]     + xv.x;
                o.y = acc[mi][ni][m8 * 2 + 1] + bo[col + 1] + xv.y;
                *(float2*)(Y + (size_t)row * EMB + col) = o;
            }
        }
}

// ---------------- Sinkhorn vector kernels (fp8 E, invert-on-load) --------------
__global__ __launch_bounds__(256) void rowmv_kernel(
    const float* __restrict__ braw, float* __restrict__ outraw)
{
    int h = blockIdx.y;
    __shared__ float bs[SEQ];
    for (int j = threadIdx.x; j < SEQ; j += 256)
        bs[j] = MU_F / braw[h * SEQ + j];
    __syncthreads();
    int w = threadIdx.x >> 5, lane = threadIdx.x & 31;
#pragma unroll
    for (int rr = 0; rr < 2; rr++) {
        int row = blockIdx.x * 16 + w * 2 + rr;
        const uint4* Ep4 = (const uint4*)(g_E8 + ((size_t)h * SEQ + row) * SEQ);
        float sum = 0.f;
#pragma unroll
        for (int k = 0; k < 4; k++) {
            int it = lane + k * 32;
            uint4 u = Ep4[it];
            int base = it * 16;
            const uint32_t wbuf[4] = {u.x, u.y, u.z, u.w};
#pragma unroll
            for (int q = 0; q < 4; q++) {
                float2 lo, hi;
                dec4(wbuf[q], lo, hi);
                sum += lo.x * bs[base + 4 * q] + lo.y * bs[base + 4 * q + 1]
                     + hi.x * bs[base + 4 * q + 2] + hi.y * bs[base + 4 * q + 3];
            }
        }
#pragma unroll
        for (int o = 16; o; o >>= 1) sum += __shfl_xor_sync(0xffffffffu, sum, o);
        if (lane == 0) outraw[h * SEQ + row] = sum;
    }
}

__global__ __launch_bounds__(128) void colmv_kernel(
    const float* __restrict__ araw, float* __restrict__ outraw)
{
    int h = blockIdx.z;
    int j = (blockIdx.x * 128 + threadIdx.x) * 4;
    int i0 = blockIdx.y * 128;
    __shared__ float as_[128];
    if (threadIdx.x < 128) as_[threadIdx.x] = MU_F / araw[h * SEQ + i0 + threadIdx.x];
    __syncthreads();
    const unsigned char* Ep = g_E8 + (size_t)h * SEQ * SEQ + (size_t)i0 * SEQ + j;
    float s0 = 0.f, s1 = 0.f, s2 = 0.f, s3 = 0.f;
#pragma unroll 4
    for (int i = 0; i < 128; i++) {
        uint32_t w = *(const uint32_t*)(Ep + (size_t)i * SEQ);
        float2 lo, hi;
        dec4(w, lo, hi);
        float a = as_[i];
        s0 += lo.x * a; s1 += lo.y * a; s2 += hi.x * a; s3 += hi.y * a;
    }
    float* c = outraw + h * SEQ + j;
    atomicAdd(c + 0, s0);
    atomicAdd(c + 1, s1);
    atomicAdd(c + 2, s2);
    atomicAdd(c + 3, s3);
}

// ---------------- LayerNorm ---------------------------------------------------
__global__ __launch_bounds__(256) void ln_kernel(
    const float* __restrict__ y, const float* __restrict__ gam,
    const float* __restrict__ bet, float* __restrict__ out)
{
    int row = blockIdx.x;
    const float* yr = y + (size_t)row * EMB;
    int t = threadIdx.x;
    float v0 = yr[t], v1 = yr[t + 256], v2 = yr[t + 512];

    __shared__ float red[8];
    int lane = t & 31, w = t >> 5;

    float s = v0 + v1 + v2;
#pragma unroll
    for (int o = 16; o; o >>= 1) s += __shfl_xor_sync(0xffffffffu, s, o);
    if (lane == 0) red[w] = s;
    __syncthreads();
    float tot = red[0] + red[1] + red[2] + red[3] + red[4] + red[5] + red[6] + red[7];
    float mean = tot * (1.0f / EMB);

    float d0 = v0 - mean, d1 = v1 - mean, d2 = v2 - mean;
    float sq = d0 * d0 + d1 * d1 + d2 * d2;
    __syncthreads();
#pragma unroll
    for (int o = 16; o; o >>= 1) sq += __shfl_xor_sync(0xffffffffu, sq, o);
    if (lane == 0) red[w] = sq;
    __syncthreads();
    float var = (red[0]+red[1]+red[2]+red[3]+red[4]+red[5]+red[6]+red[7]) * (1.0f / EMB);
    float inv = rsqrtf(var + 1e-12f);

    float* outr = out + (size_t)row * EMB;
    outr[t]       = gam[t]       * d0 * inv + bet[t];
    outr[t + 256] = gam[t + 256] * d1 * inv + bet[t + 256];
    outr[t + 512] = gam[t + 512] * d2 * inv + bet[t + 512];
}

// ---------------- launch ------------------------------------------------------
extern "C" void kernel_launch(void* const* d_in, const int* in_sizes, int n_in,
                              void* d_out, int out_size)
{
    const float* X  = (const float*)d_in[0];
    const float* Wq = (const float*)d_in[1];
    const float* bq = (const float*)d_in[2];
    const float* Wk = (const float*)d_in[3];
    const float* bk = (const float*)d_in[4];
    const float* Wv = (const float*)d_in[5];
    const float* bv = (const float*)d_in[6];
    const float* Wo = (const float*)d_in[7];
    const float* bo = (const float*)d_in[8];
    const float* lg = (const float*)d_in[9];
    const float* lb = (const float*)d_in[10];
    float* out = (float*)d_out;

    void *pXb, *pWt, *pQKV, *pVt, *pctx, *pr, *py;
    cudaGetSymbolAddress(&pXb, g_Xb);
    cudaGetSymbolAddress(&pWt, g_Wt);
    cudaGetSymbolAddress(&pQKV, g_QKV);
    cudaGetSymbolAddress(&pVt, g_Vt8);
    cudaGetSymbolAddress(&pctx, g_ctxb);
    cudaGetSymbolAddress(&pr, g_r);
    cudaGetSymbolAddress(&py, g_y);

    __nv_bfloat16* Xb  = (__nv_bfloat16*)pXb;
    __nv_bfloat16* Wt  = (__nv_bfloat16*)pWt;
    __nv_bfloat16* QKV = (__nv_bfloat16*)pQKV;
    unsigned char* Vt  = (unsigned char*)pVt;
    __nv_bfloat16* ctx = (__nv_bfloat16*)pctx;
    float* fr = (float*)pr;
    float* fy = (float*)py;

    float* r0 = fr + 0 * NH * SEQ;
    float* r1 = fr + 1 * NH * SEQ;
    float* r2 = fr + 2 * NH * SEQ;
    float* r3 = fr + 3 * NH * SEQ;
    float* r4 = fr + 4 * NH * SEQ;
    float* r5 = fr + 5 * NH * SEQ;

    cudaFuncSetAttribute(proj_kernel,  cudaFuncAttributeMaxDynamicSharedMemorySize, SMEM_GEMM);
    cudaFuncSetAttribute(qk_kernel,    cudaFuncAttributeMaxDynamicSharedMemorySize, SMEM_GEMM);
    cudaFuncSetAttribute(av_kernel,    cudaFuncAttributeMaxDynamicSharedMemorySize, SMEM_AV);
    cudaFuncSetAttribute(final_kernel, cudaFuncAttributeMaxDynamicSharedMemorySize, SMEM_GEMM);

    prep_kernel<<<576 + 1536 + 2304, 256>>>(X, Wq, Wk, Wv, Wo, Xb, Wt, fr);

    proj_kernel<<<dim3(EMB / 128, SEQ / 128, 3), 256, SMEM_GEMM>>>(Xb, Wt, bq, bk, bv, QKV);

    qk_kernel<<<dim3(SEQ / 128, SEQ / 128, NH), 256, SMEM_GEMM>>>(QKV, r0);

    // Sinkhorn: 3 iterations, raw sums, inversion folded into consumers
    colmv_kernel<<<dim3(SEQ / 512, 16, NH), 128>>>(r0, r1);
    rowmv_kernel<<<dim3(SEQ / 16, NH), 256>>>(r1, r2);
    colmv_kernel<<<dim3(SEQ / 512, 16, NH), 128>>>(r2, r3);
    rowmv_kernel<<<dim3(SEQ / 16, NH), 256>>>(r3, r4);
    colmv_kernel<<<dim3(SEQ / 512, 16, NH), 128>>>(r4, r5);

    vt_prep_kernel<<<dim3(SEQ / 64, NH), 256>>>(QKV + (size_t)2 * SEQ * EMB, r5, Vt);

    av_kernel<<<dim3(SEQ / 128, NH), 256, SMEM_AV>>>(Vt, r4, ctx);

    final_kernel<<<dim3(EMB / 128, SEQ / 128), 256, SMEM_GEMM>>>(ctx, Wt, bo, X, fy);

    ln_kernel<<<SEQ, 256>>>(fy, lg, lb, out);
}

// round 9
// speedup vs baseline: 5.0380x; 1.0091x over previous
#include <cuda_runtime.h>
#include <cuda_bf16.h>
#include <cuda_fp16.h>
#include <cstdint>
#include <cstddef>

#define SEQ 2048
#define EMB 768
#define NH  12
#define HD  64
#define MU_F (1.0f/2048.0f)
#define PADK 40     // bf16 GEMM smem row stride (elements)
#define APAD 48     // fp8 av smem row stride (bytes)
#define VSCALE 16.0f

// sink-pass tiling
#define TROWS 16
#define TPAD  2064
#define TILEB (TROWS * TPAD)            // 33024
#define SINK_ROWS 64
#define SINK_NT (SINK_ROWS / TROWS)     // 4
#define SMEM_SINK (2048 * 4 + 2 * TILEB + 64)   // 74304

// ---------------- scratch (device globals; no allocation allowed) -------------
__device__ __nv_bfloat16 g_Xb[SEQ*EMB];
__device__ __nv_bfloat16 g_Wt[4*EMB*EMB];           // Wq,Wk,Wv,Wo transposed [n][k]
__device__ __nv_bfloat16 g_QKV[3*SEQ*EMB];          // Q(=q/8), K, V  bf16
__device__ unsigned char g_E8[(size_t)NH*SEQ*SEQ];  // exp(QK^T/8) e4m3 (50.3MB)
__device__ unsigned char g_Vt8[NH*HD*SEQ];          // (diag(b) V)^T * 16, e4m3
__device__ __nv_bfloat16 g_ctxb[SEQ*EMB];
__device__ float g_r[6*NH*SEQ];                     // raw Sinkhorn sums r0..r5
__device__ float g_y[SEQ*EMB];

// ============================ PTX helpers =====================================
__device__ __forceinline__ uint32_t smem_u32(const void* p) {
    uint32_t a;
    asm("{ .reg .u64 t; cvta.to.shared.u64 t, %1; cvt.u32.u64 %0, t; }"
        : "=r"(a) : "l"(p));
    return a;
}
__device__ __forceinline__ void cpa16(uint32_t dst, const void* src) {
    asm volatile("cp.async.cg.shared.global [%0], [%1], 16;" :: "r"(dst), "l"(src));
}
#define CP_COMMIT() asm volatile("cp.async.commit_group;" ::: "memory")
#define CP_WAIT1()  asm volatile("cp.async.wait_group 1;" ::: "memory")
#define CP_WAIT0()  asm volatile("cp.async.wait_group 0;" ::: "memory")

__device__ __forceinline__ void ldsm4(uint32_t& r0, uint32_t& r1, uint32_t& r2,
                                      uint32_t& r3, uint32_t addr) {
    asm volatile("ldmatrix.sync.aligned.m8n8.x4.shared.b16 {%0,%1,%2,%3}, [%4];"
        : "=r"(r0), "=r"(r1), "=r"(r2), "=r"(r3) : "r"(addr));
}
__device__ __forceinline__ void mma16816(float* c, const uint32_t* a, const uint32_t* b) {
    asm volatile("mma.sync.aligned.m16n8k16.row.col.f32.bf16.bf16.f32 "
        "{%0,%1,%2,%3}, {%4,%5,%6,%7}, {%8,%9}, {%0,%1,%2,%3};"
        : "+f"(c[0]), "+f"(c[1]), "+f"(c[2]), "+f"(c[3])
        : "r"(a[0]), "r"(a[1]), "r"(a[2]), "r"(a[3]), "r"(b[0]), "r"(b[1]));
}
__device__ __forceinline__ void mma16832q(float* c, const uint32_t* a, const uint32_t* b) {
    asm volatile("mma.sync.aligned.m16n8k32.row.col.f32.e4m3.e4m3.f32 "
        "{%0,%1,%2,%3}, {%4,%5,%6,%7}, {%8,%9}, {%0,%1,%2,%3};"
        : "+f"(c[0]), "+f"(c[1]), "+f"(c[2]), "+f"(c[3])
        : "r"(a[0]), "r"(a[1]), "r"(a[2]), "r"(a[3]), "r"(b[0]), "r"(b[1]));
}

// fp8 e4m3 pack/unpack
__device__ __forceinline__ uint16_t pk_e4m3(float lo, float hi) {
    uint16_t r;
    asm("cvt.rn.satfinite.e4m3x2.f32 %0, %1, %2;" : "=h"(r) : "f"(hi), "f"(lo));
    return r;
}
__device__ __forceinline__ void dec4(uint32_t w, float2& lo, float2& hi) {
    uint32_t f0, f1;
    asm("cvt.rn.f16x2.e4m3x2 %0, %1;" : "=r"(f0) : "h"((uint16_t)(w & 0xffffu)));
    asm("cvt.rn.f16x2.e4m3x2 %0, %1;" : "=r"(f1) : "h"((uint16_t)(w >> 16)));
    lo = __half22float2(*(__half2*)&f0);
    hi = __half22float2(*(__half2*)&f1);
}

// ---------------- mma.sync block-GEMM core, 3-stage pipeline (bf16) ------------
template<int BN>
__device__ __forceinline__ void gemm_core3(
    const __nv_bfloat16* __restrict__ A, int lda,
    const __nv_bfloat16* __restrict__ B, int ldb,
    int nchunks, __nv_bfloat16* As, __nv_bfloat16* Bs,
    float acc[2][BN/16][4])
{
    constexpr int NF = BN / 16;
    const int tid = threadIdx.x;
    const int lane = tid & 31, wid = tid >> 5;
    const int wm = wid >> 1, wn = wid & 1;
    const uint32_t asb = smem_u32(As), bsb = smem_u32(Bs);
    const uint32_t ASTG = 128 * PADK * 2, BSTG = BN * PADK * 2;

    const int lr = tid >> 2, lc = (tid & 3) * 8;
    const uint32_t adst = (uint32_t)(lr * PADK + lc) * 2;
    const uint32_t bdst = adst;

    uint32_t aoff[2], boff[NF / 2];
#pragma unroll
    for (int mi = 0; mi < 2; mi++) {
        int r = wm * 32 + mi * 16 + (lane & 15);
        int c = (lane >> 4) * 8;
        aoff[mi] = (uint32_t)(r * PADK + c) * 2;
    }
#pragma unroll
    for (int n2 = 0; n2 < NF / 2; n2++) {
        int g = lane >> 3;
        int r = wn * (BN / 2) + n2 * 16 + ((g >> 1) << 3) + (lane & 7);
        int c = (g & 1) * 8;
        boff[n2] = (uint32_t)(r * PADK + c) * 2;
    }

#pragma unroll
    for (int mi = 0; mi < 2; mi++)
#pragma unroll
        for (int ni = 0; ni < NF; ni++)
#pragma unroll
            for (int q = 0; q < 4; q++) acc[mi][ni][q] = 0.f;

    auto issue = [&](int c, int stg) {
        const __nv_bfloat16* Ac = A + c * 32;
        const __nv_bfloat16* Bc = B + c * 32;
        uint32_t ad = asb + (uint32_t)stg * ASTG, bd = bsb + (uint32_t)stg * BSTG;
        cpa16(ad + adst, Ac + (size_t)lr * lda + lc);
        cpa16(ad + adst + 64u * PADK * 2, Ac + (size_t)(lr + 64) * lda + lc);
        cpa16(bd + bdst, Bc + (size_t)lr * ldb + lc);
        if (BN == 128)
            cpa16(bd + bdst + 64u * PADK * 2, Bc + (size_t)(lr + 64) * ldb + lc);
        CP_COMMIT();
    };

    issue(0, 0);
    if (nchunks > 1) issue(1, 1);

    int s = 0, w = 2;
    for (int c = 0; c < nchunks; c++) {
        if (c + 1 < nchunks) { CP_WAIT1(); } else { CP_WAIT0(); }
        __syncthreads();
        if (c + 2 < nchunks) issue(c + 2, w);

        uint32_t ab = asb + (uint32_t)s * ASTG, bb = bsb + (uint32_t)s * BSTG;
#pragma unroll
        for (int ks = 0; ks < 2; ks++) {
            uint32_t af[2][4];
            ldsm4(af[0][0], af[0][1], af[0][2], af[0][3], ab + aoff[0] + ks * 32);
            ldsm4(af[1][0], af[1][1], af[1][2], af[1][3], ab + aoff[1] + ks * 32);
#pragma unroll
            for (int n2 = 0; n2 < NF / 2; n2++) {
                uint32_t bf[4];
                ldsm4(bf[0], bf[1], bf[2], bf[3], bb + boff[n2] + ks * 32);
                mma16816(acc[0][2 * n2],     af[0], bf + 0);
                mma16816(acc[0][2 * n2 + 1], af[0], bf + 2);
                mma16816(acc[1][2 * n2],     af[1], bf + 0);
                mma16816(acc[1][2 * n2 + 1], af[1], bf + 2);
            }
        }
        s = (s == 2) ? 0 : s + 1;
        w = (w == 2) ? 0 : w + 1;
    }
}

#define SMEM_GEMM (6 * 128 * PADK * 2)                      // 61440
#define SMEM_AV   (3 * 128 * APAD + 3 * 64 * APAD)          // 27648

// ---------------- fused prep: zero r, cvt X->bf16, transpose W -----------------
__global__ __launch_bounds__(256) void prep_kernel(
    const float* __restrict__ X,
    const float* __restrict__ Wq, const float* __restrict__ Wk,
    const float* __restrict__ Wv, const float* __restrict__ Wo,
    __nv_bfloat16* __restrict__ Xb, __nv_bfloat16* __restrict__ Wt,
    float* __restrict__ r)
{
    __shared__ float t[32][33];
    int b = blockIdx.x;
    if (b < 576) {                       // zero 6*NH*SEQ floats
        r[b * 256 + threadIdx.x] = 0.f;
        return;
    }
    b -= 576;
    if (b < 1536) {                      // cvt X
        int i = (b * 256 + threadIdx.x) * 4;
        float4 v = *(const float4*)(X + i);
        __nv_bfloat162 p0 = __floats2bfloat162_rn(v.x, v.y);
        __nv_bfloat162 p1 = __floats2bfloat162_rn(v.z, v.w);
        uint2 o = make_uint2(*(uint32_t*)&p0, *(uint32_t*)&p1);
        *(uint2*)(Xb + i) = o;
        return;
    }
    b -= 1536;                           // wtrans: 4 * 24 * 24 blocks
    int z = b / 576;
    int rem = b % 576;
    int n0 = (rem % 24) * 32, k0 = (rem / 24) * 32;
    const float* W = (z == 0) ? Wq : (z == 1) ? Wk : (z == 2) ? Wv : Wo;
    int tx = threadIdx.x & 31, ty = threadIdx.x >> 5;
#pragma unroll
    for (int q = 0; q < 4; q++)
        t[ty + q * 8][tx] = W[(size_t)(k0 + ty + q * 8) * EMB + n0 + tx];
    __syncthreads();
    __nv_bfloat16* O = Wt + (size_t)z * EMB * EMB;
#pragma unroll
    for (int q = 0; q < 4; q++)
        O[(size_t)(n0 + ty + q * 8) * EMB + k0 + tx] = __float2bfloat16(t[tx][ty + q * 8]);
}

// Vt8[h][d][j] = e4m3( V[j][h*64+d] * (MU / r5_raw[h][j]) * 16 )
__global__ __launch_bounds__(256) void vt_prep_kernel(
    const __nv_bfloat16* __restrict__ Vb, const float* __restrict__ braw,
    unsigned char* __restrict__ Vt)
{
    int h = blockIdx.y, j0 = blockIdx.x * 64;
    __shared__ float t[64][65];
    int tid = threadIdx.x;
    int jj = tid >> 2, d0 = (tid & 3) * 16;
    const __nv_bfloat16* src = Vb + (size_t)(j0 + jj) * EMB + h * HD + d0;
    __nv_bfloat16 tmp[16];
    *(uint4*)tmp = *(const uint4*)src;
    *(uint4*)(tmp + 8) = *(const uint4*)(src + 8);
#pragma unroll
    for (int q = 0; q < 16; q++) t[jj][d0 + q] = __bfloat162float(tmp[q]);
    __syncthreads();
    int dd = tid >> 2, jb = (tid & 3) * 16;
    uint16_t o[8];
#pragma unroll
    for (int q = 0; q < 8; q++) {
        int j = j0 + jb + 2 * q;
        float b0 = VSCALE * MU_F / braw[h * SEQ + j];
        float b1 = VSCALE * MU_F / braw[h * SEQ + j + 1];
        o[q] = pk_e4m3(t[jb + 2 * q][dd] * b0, t[jb + 2 * q + 1][dd] * b1);
    }
    unsigned char* dst = Vt + ((size_t)h * HD + dd) * SEQ + j0 + jb;
    *(uint4*)dst = *(uint4*)o;
}

// ---------------- QKV projection ----------------------------------------------
__global__ __launch_bounds__(256, 2) void proj_kernel(
    const __nv_bfloat16* __restrict__ Xb, const __nv_bfloat16* __restrict__ Wt,
    const float* __restrict__ bq, const float* __restrict__ bk,
    const float* __restrict__ bv, __nv_bfloat16* __restrict__ Out)
{
    extern __shared__ char dsm[];
    __nv_bfloat16* As = (__nv_bfloat16*)dsm;
    __nv_bfloat16* Bs = (__nv_bfloat16*)(dsm + 3 * 128 * PADK * 2);
    int z = blockIdx.z;
    int n0 = blockIdx.x * 128, i0 = blockIdx.y * 128;
    const float* bias = (z == 0) ? bq : (z == 1) ? bk : bv;
    float scale = (z == 0) ? 0.125f : 1.0f;

    float acc[2][8][4];
    gemm_core3<128>(Xb + (size_t)i0 * EMB, EMB,
                    Wt + (size_t)z * EMB * EMB + (size_t)n0 * EMB, EMB,
                    EMB / 32, As, Bs, acc);

    int lane = threadIdx.x & 31, wid = threadIdx.x >> 5;
    int wm = wid >> 1, wn = wid & 1;
    int r0 = wm * 32 + (lane >> 2), cb = wn * 64 + (lane & 3) * 2;
    __nv_bfloat16* O = Out + (size_t)z * SEQ * EMB;
#pragma unroll
    for (int mi = 0; mi < 2; mi++)
#pragma unroll
        for (int m8 = 0; m8 < 2; m8++) {
            int row = i0 + r0 + mi * 16 + m8 * 8;
#pragma unroll
            for (int ni = 0; ni < 8; ni++) {
                int col = n0 + cb + ni * 8;
                float f0 = (acc[mi][ni][m8 * 2 + 0] + bias[col])     * scale;
                float f1 = (acc[mi][ni][m8 * 2 + 1] + bias[col + 1]) * scale;
                __nv_bfloat162 p = __floats2bfloat162_rn(f0, f1);
                *(uint32_t*)(O + (size_t)row * EMB + col) = *(uint32_t*)&p;
            }
        }
}

// ---------------- E = exp(QK^T/8) (e4m3) + raw row sums -> r0 ------------------
__global__ __launch_bounds__(256, 2) void qk_kernel(
    const __nv_bfloat16* __restrict__ QKV, float* __restrict__ rsumg)
{
    extern __shared__ char dsm[];
    __nv_bfloat16* As = (__nv_bfloat16*)dsm;
    __nv_bfloat16* Bs = (__nv_bfloat16*)(dsm + 3 * 128 * PADK * 2);
    int j0 = blockIdx.x * 128, i0 = blockIdx.y * 128, h = blockIdx.z;

    float acc[2][8][4];
    gemm_core3<128>(QKV + (size_t)i0 * EMB + h * HD, EMB,
                    QKV + (size_t)SEQ * EMB + (size_t)j0 * EMB + h * HD, EMB,
                    HD / 32, As, Bs, acc);

    unsigned char* Et = (unsigned char*)dsm;
    float* rsumS = (float*)(dsm + 128 * 144);
    int tid = threadIdx.x, lane = tid & 31, wid = tid >> 5;
    int wm = wid >> 1, wn = wid & 1;
    int r0 = wm * 32 + (lane >> 2), cb = wn * 64 + (lane & 3) * 2;

    __syncthreads();
    if (tid < 128) rsumS[tid] = 0.f;

    float rs_sv[4];
    int lrow_sv[4];
    int idx = 0;
#pragma unroll
    for (int mi = 0; mi < 2; mi++)
#pragma unroll
        for (int m8 = 0; m8 < 2; m8++) {
            int lrow = r0 + mi * 16 + m8 * 8;
            float rs = 0.f;
#pragma unroll
            for (int ni = 0; ni < 8; ni++) {
                float e0 = __expf(acc[mi][ni][m8 * 2 + 0]);
                float e1 = __expf(acc[mi][ni][m8 * 2 + 1]);
                rs += e0 + e1;
                *(uint16_t*)(Et + lrow * 144 + cb + ni * 8) = pk_e4m3(e0, e1);
            }
            rs += __shfl_xor_sync(0xffffffffu, rs, 1);
            rs += __shfl_xor_sync(0xffffffffu, rs, 2);
            rs_sv[idx] = rs; lrow_sv[idx] = lrow; idx++;
        }
    __syncthreads();
#pragma unroll
    for (int q = 0; q < 4; q++)
        if ((lane & 3) == 0) atomicAdd(&rsumS[lrow_sv[q]], rs_sv[q]);
    __syncthreads();

    int row = tid >> 1, half = (tid & 1) * 64;
    const uint4* src = (const uint4*)(Et + row * 144 + half);
    uint4* dst = (uint4*)(g_E8 + ((size_t)h * SEQ + i0 + row) * SEQ + j0 + half);
    dst[0] = src[0]; dst[1] = src[1]; dst[2] = src[2]; dst[3] = src[3];
    if (tid < 128)
        atomicAdd(&rsumg[h * SEQ + i0 + tid], rsumS[tid]);
}

// ---------------- Sinkhorn streaming pass (fused row+col, cp.async tiles) ------
// DO_ROW=true : rowout[i] = s_i = sum_j E_ij*(MU/inraw[j]); colout[j] += E_ij*(MU/s_i)
// DO_ROW=false: colout[j] += E_ij*(MU/inraw[i])  (inraw row-indexed)
template<bool DO_ROW>
__global__ __launch_bounds__(256) void sink_pass(
    const float* __restrict__ inraw, float* __restrict__ rowout,
    float* __restrict__ colout)
{
    extern __shared__ char sm[];
    float* bs = (float*)sm;                          // 2048 floats
    char* tiles = sm + 2048 * 4;                     // 2 x TILEB
    float* arow = (float*)(sm + 2048 * 4 + 2 * TILEB);  // 16 floats
    int h = blockIdx.y, i0 = blockIdx.x * SINK_ROWS;
    int tid = threadIdx.x, lane = tid & 31, wid = tid >> 5;

    if (DO_ROW) {
        for (int j = tid; j < SEQ; j += 256) bs[j] = MU_F / inraw[h * SEQ + j];
    }

    const int lrow = tid >> 4, lcb = (tid & 15) * 16;
    const unsigned char* Eb = g_E8 + ((size_t)h * SEQ + i0) * SEQ;
    const uint32_t tbase = smem_u32(tiles);

    auto issue = [&](int t, int stg) {
        const unsigned char* src = Eb + (size_t)(t * TROWS + lrow) * SEQ + lcb;
        uint32_t dst = tbase + (uint32_t)stg * TILEB + lrow * TPAD + lcb;
#pragma unroll
        for (int it = 0; it < 8; it++) cpa16(dst + it * 256, src + it * 256);
        CP_COMMIT();
    };

    float ac[8];
#pragma unroll
    for (int q = 0; q < 8; q++) ac[q] = 0.f;

    issue(0, 0);

    for (int t = 0; t < SINK_NT; t++) {
        int s = t & 1;
        if (t + 1 < SINK_NT) { issue(t + 1, s ^ 1); CP_WAIT1(); }
        else { CP_WAIT0(); }
        __syncthreads();

        if (DO_ROW) {
#pragma unroll
            for (int rr = 0; rr < 2; rr++) {
                int row = wid * 2 + rr;
                const char* trow = tiles + s * TILEB + row * TPAD;
                float sum = 0.f;
#pragma unroll
                for (int k = 0; k < 4; k++) {
                    int colb = lane * 16 + k * 512;
                    uint4 u = *(const uint4*)(trow + colb);
                    const uint32_t wv[4] = {u.x, u.y, u.z, u.w};
#pragma unroll
                    for (int m = 0; m < 4; m++) {
                        float2 lo, hi;
                        dec4(wv[m], lo, hi);
                        const float* bp = bs + colb + m * 4;
                        sum += lo.x * bp[0] + lo.y * bp[1] + hi.x * bp[2] + hi.y * bp[3];
                    }
                }
#pragma unroll
                for (int o = 16; o; o >>= 1) sum += __shfl_xor_sync(0xffffffffu, sum, o);
                if (lane == 0) {
                    rowout[h * SEQ + i0 + t * TROWS + row] = sum;
                    arow[row] = MU_F / sum;
                }
            }
        } else {
            if (tid < TROWS)
                arow[tid] = MU_F / inraw[h * SEQ + i0 + t * TROWS + tid];
        }
        __syncthreads();

        // column accumulate: thread owns cols tid*8 .. tid*8+7
#pragma unroll
        for (int r = 0; r < TROWS; r++) {
            uint2 u = *(const uint2*)(tiles + s * TILEB + r * TPAD + tid * 8);
            float a = arow[r];
            float2 lo, hi, lo2, hi2;
            dec4(u.x, lo, hi);
            dec4(u.y, lo2, hi2);
            ac[0] += lo.x * a;  ac[1] += lo.y * a;
            ac[2] += hi.x * a;  ac[3] += hi.y * a;
            ac[4] += lo2.x * a; ac[5] += lo2.y * a;
            ac[6] += hi2.x * a; ac[7] += hi2.y * a;
        }
        __syncthreads();
    }

    float* cp = colout + h * SEQ + tid * 8;
#pragma unroll
    for (int q = 0; q < 8; q++) atomicAdd(cp + q, ac[q]);
}

// ---------------- ctx = diag(1/r4) * E * (diag(b) V)  — native fp8 mma ---------
__global__ __launch_bounds__(256, 2) void av_kernel(
    const unsigned char* __restrict__ Vt, const float* __restrict__ araw,
    __nv_bfloat16* __restrict__ ctx)
{
    extern __shared__ char dsm[];
    char* As = dsm;                      // 3 stages 128 x APAD
    char* Bs = dsm + 3 * 128 * APAD;     // 3 stages 64 x APAD
    int i0 = blockIdx.x * 128, h = blockIdx.y;
    const int tid = threadIdx.x, lane = tid & 31, wid = tid >> 5;
    const int wm = wid >> 1, wn = wid & 1;
    const uint32_t asb = smem_u32(As), bsb = smem_u32(Bs);
    const uint32_t ASTG = 128 * APAD, BSTG = 64 * APAD;
    const int NCH = SEQ / 32;

    const int arow = tid >> 1, acol = (tid & 1) * 16;
    const unsigned char* Ag = g_E8 + ((size_t)h * SEQ + i0 + arow) * SEQ + acol;
    const uint32_t adst = (uint32_t)(arow * APAD + acol);
    const int brow = tid >> 1, bcol = (tid & 1) * 16;
    const unsigned char* Bg = Vt + ((size_t)h * HD + brow) * SEQ + bcol;
    const uint32_t bdst = (uint32_t)(brow * APAD + bcol);
    const bool bload = (tid < 128);

    uint32_t aoff[2], boff[2];
#pragma unroll
    for (int mi = 0; mi < 2; mi++) {
        int r = wm * 32 + mi * 16 + (lane & 15);
        aoff[mi] = (uint32_t)(r * APAD + (lane >> 4) * 16);
    }
#pragma unroll
    for (int n2 = 0; n2 < 2; n2++) {
        int g = lane >> 3;
        int r = wn * 32 + n2 * 16 + ((g >> 1) << 3) + (lane & 7);
        boff[n2] = (uint32_t)(r * APAD + (g & 1) * 16);
    }

    float acc[2][4][4];
#pragma unroll
    for (int mi = 0; mi < 2; mi++)
#pragma unroll
        for (int ni = 0; ni < 4; ni++)
#pragma unroll
            for (int q = 0; q < 4; q++) acc[mi][ni][q] = 0.f;

    auto issue = [&](int c, int stg) {
        cpa16(asb + (uint32_t)stg * ASTG + adst, Ag + c * 32);
        if (bload) cpa16(bsb + (uint32_t)stg * BSTG + bdst, Bg + c * 32);
        CP_COMMIT();
    };

    issue(0, 0);
    issue(1, 1);

    int s = 0, w = 2;
    for (int c = 0; c < NCH; c++) {
        if (c + 1 < NCH) { CP_WAIT1(); } else { CP_WAIT0(); }
        __syncthreads();
        if (c + 2 < NCH) issue(c + 2, w);

        uint32_t ab = asb + (uint32_t)s * ASTG, bb = bsb + (uint32_t)s * BSTG;
        uint32_t af[2][4];
        ldsm4(af[0][0], af[0][1], af[0][2], af[0][3], ab + aoff[0]);
        ldsm4(af[1][0], af[1][1], af[1][2], af[1][3], ab + aoff[1]);
#pragma unroll
        for (int n2 = 0; n2 < 2; n2++) {
            uint32_t bf[4];
            ldsm4(bf[0], bf[1], bf[2], bf[3], bb + boff[n2]);
            mma16832q(acc[0][2 * n2],     af[0], bf + 0);
            mma16832q(acc[0][2 * n2 + 1], af[0], bf + 2);
            mma16832q(acc[1][2 * n2],     af[1], bf + 0);
            mma16832q(acc[1][2 * n2 + 1], af[1], bf + 2);
        }
        s = (s == 2) ? 0 : s + 1;
        w = (w == 2) ? 0 : w + 1;
    }

    int r0 = wm * 32 + (lane >> 2), cb = wn * 32 + (lane & 3) * 2;
#pragma unroll
    for (int mi = 0; mi < 2; mi++)
#pragma unroll
        for (int m8 = 0; m8 < 2; m8++) {
            int row = i0 + r0 + mi * 16 + m8 * 8;
            float sc = 1.0f / (araw[h * SEQ + row] * VSCALE);
            __nv_bfloat16* O = ctx + (size_t)row * EMB + h * HD;
#pragma unroll
            for (int ni = 0; ni < 4; ni++) {
                float f0 = acc[mi][ni][m8 * 2 + 0] * sc;
                float f1 = acc[mi][ni][m8 * 2 + 1] * sc;
                __nv_bfloat162 p = __floats2bfloat162_rn(f0, f1);
                *(uint32_t*)(O + cb + ni * 8) = *(uint32_t*)&p;
            }
        }
}

// ---------------- y = ctx @ Wo + bo + X ----------------------------------------
__global__ __launch_bounds__(256, 2) void final_kernel(
    const __nv_bfloat16* __restrict__ ctx, const __nv_bfloat16* __restrict__ Wt,
    const float* __restrict__ bo, const float* __restrict__ X,
    float* __restrict__ Y)
{
    extern __shared__ char dsm[];
    __nv_bfloat16* As = (__nv_bfloat16*)dsm;
    __nv_bfloat16* Bs = (__nv_bfloat16*)(dsm + 3 * 128 * PADK * 2);
    int n0 = blockIdx.x * 128, i0 = blockIdx.y * 128;

    float acc[2][8][4];
    gemm_core3<128>(ctx + (size_t)i0 * EMB, EMB,
                    Wt + (size_t)3 * EMB * EMB + (size_t)n0 * EMB, EMB,
                    EMB / 32, As, Bs, acc);

    int lane = threadIdx.x & 31, wid = threadIdx.x >> 5;
    int wm = wid >> 1, wn = wid & 1;
    int r0 = wm * 32 + (lane >> 2), cb = wn * 64 + (lane & 3) * 2;
#pragma unroll
    for (int mi = 0; mi < 2; mi++)
#pragma unroll
        for (int m8 = 0; m8 < 2; m8++) {
            int row = i0 + r0 + mi * 16 + m8 * 8;
#pragma unroll
            for (int ni = 0; ni < 8; ni++) {
                int col = n0 + cb + ni * 8;
                float2 xv = *(const float2*)(X + (size_t)row * EMB + col);
                float2 o;
                o.x = acc[mi][ni][m8 * 2 + 0] + bo[col]     + xv.x;
                o.y = acc[mi][ni][m8 * 2 + 1] + bo[col + 1] + xv.y;
                *(float2*)(Y + (size_t)row * EMB + col) = o;
            }
        }
}

// ---------------- LayerNorm ---------------------------------------------------
__global__ __launch_bounds__(256) void ln_kernel(
    const float* __restrict__ y, const float* __restrict__ gam,
    const float* __restrict__ bet, float* __restrict__ out)
{
    int row = blockIdx.x;
    const float* yr = y + (size_t)row * EMB;
    int t = threadIdx.x;
    float v0 = yr[t], v1 = yr[t + 256], v2 = yr[t + 512];

    __shared__ float red[8];
    int lane = t & 31, w = t >> 5;

    float s = v0 + v1 + v2;
#pragma unroll
    for (int o = 16; o; o >>= 1) s += __shfl_xor_sync(0xffffffffu, s, o);
    if (lane == 0) red[w] = s;
    __syncthreads();
    float tot = red[0] + red[1] + red[2] + red[3] + red[4] + red[5] + red[6] + red[7];
    float mean = tot * (1.0f / EMB);

    float d0 = v0 - mean, d1 = v1 - mean, d2 = v2 - mean;
    float sq = d0 * d0 + d1 * d1 + d2 * d2;
    __syncthreads();
#pragma unroll
    for (int o = 16; o; o >>= 1) sq += __shfl_xor_sync(0xffffffffu, sq, o);
    if (lane == 0) red[w] = sq;
    __syncthreads();
    float var = (red[0]+red[1]+red[2]+red[3]+red[4]+red[5]+red[6]+red[7]) * (1.0f / EMB);
    float inv = rsqrtf(var + 1e-12f);

    float* outr = out + (size_t)row * EMB;
    outr[t]       = gam[t]       * d0 * inv + bet[t];
    outr[t + 256] = gam[t + 256] * d1 * inv + bet[t + 256];
    outr[t + 512] = gam[t + 512] * d2 * inv + bet[t + 512];
}

// ---------------- launch ------------------------------------------------------
extern "C" void kernel_launch(void* const* d_in, const int* in_sizes, int n_in,
                              void* d_out, int out_size)
{
    const float* X  = (const float*)d_in[0];
    const float* Wq = (const float*)d_in[1];
    const float* bq = (const float*)d_in[2];
    const float* Wk = (const float*)d_in[3];
    const float* bk = (const float*)d_in[4];
    const float* Wv = (const float*)d_in[5];
    const float* bv = (const float*)d_in[6];
    const float* Wo = (const float*)d_in[7];
    const float* bo = (const float*)d_in[8];
    const float* lg = (const float*)d_in[9];
    const float* lb = (const float*)d_in[10];
    float* out = (float*)d_out;

    void *pXb, *pWt, *pQKV, *pVt, *pctx, *pr, *py;
    cudaGetSymbolAddress(&pXb, g_Xb);
    cudaGetSymbolAddress(&pWt, g_Wt);
    cudaGetSymbolAddress(&pQKV, g_QKV);
    cudaGetSymbolAddress(&pVt, g_Vt8);
    cudaGetSymbolAddress(&pctx, g_ctxb);
    cudaGetSymbolAddress(&pr, g_r);
    cudaGetSymbolAddress(&py, g_y);

    __nv_bfloat16* Xb  = (__nv_bfloat16*)pXb;
    __nv_bfloat16* Wt  = (__nv_bfloat16*)pWt;
    __nv_bfloat16* QKV = (__nv_bfloat16*)pQKV;
    unsigned char* Vt  = (unsigned char*)pVt;
    __nv_bfloat16* ctx = (__nv_bfloat16*)pctx;
    float* fr = (float*)pr;
    float* fy = (float*)py;

    float* r0 = fr + 0 * NH * SEQ;
    float* r1 = fr + 1 * NH * SEQ;
    float* r2 = fr + 2 * NH * SEQ;
    float* r3 = fr + 3 * NH * SEQ;
    float* r4 = fr + 4 * NH * SEQ;
    float* r5 = fr + 5 * NH * SEQ;

    cudaFuncSetAttribute(proj_kernel,  cudaFuncAttributeMaxDynamicSharedMemorySize, SMEM_GEMM);
    cudaFuncSetAttribute(qk_kernel,    cudaFuncAttributeMaxDynamicSharedMemorySize, SMEM_GEMM);
    cudaFuncSetAttribute(av_kernel,    cudaFuncAttributeMaxDynamicSharedMemorySize, SMEM_AV);
    cudaFuncSetAttribute(final_kernel, cudaFuncAttributeMaxDynamicSharedMemorySize, SMEM_GEMM);
    cudaFuncSetAttribute(sink_pass<true>,  cudaFuncAttributeMaxDynamicSharedMemorySize, SMEM_SINK);
    cudaFuncSetAttribute(sink_pass<false>, cudaFuncAttributeMaxDynamicSharedMemorySize, SMEM_SINK);

    prep_kernel<<<576 + 1536 + 2304, 256>>>(X, Wq, Wk, Wv, Wo, Xb, Wt, fr);

    proj_kernel<<<dim3(EMB / 128, SEQ / 128, 3), 256, SMEM_GEMM>>>(Xb, Wt, bq, bk, bv, QKV);

    qk_kernel<<<dim3(SEQ / 128, SEQ / 128, NH), 256, SMEM_GEMM>>>(QKV, r0);

    // Sinkhorn: 3 iterations in 3 E passes (col, fused row+col, fused row+col)
    dim3 gsink(SEQ / SINK_ROWS, NH);     // (32, 12)
    sink_pass<false><<<gsink, 256, SMEM_SINK>>>(r0, nullptr, r1);
    sink_pass<true><<<gsink, 256, SMEM_SINK>>>(r1, r2, r3);
    sink_pass<true><<<gsink, 256, SMEM_SINK>>>(r3, r4, r5);

    vt_prep_kernel<<<dim3(SEQ / 64, NH), 256>>>(QKV + (size_t)2 * SEQ * EMB, r5, Vt);

    av_kernel<<<dim3(SEQ / 128, NH), 256, SMEM_AV>>>(Vt, r4, ctx);

    final_kernel<<<dim3(EMB / 128, SEQ / 128), 256, SMEM_GEMM>>>(ctx, Wt, bo, X, fy);

    ln_kernel<<<SEQ, 256>>>(fy, lg, lb, out);
}